// round 7
// baseline (speedup 1.0000x reference)
#include <cuda_runtime.h>

#define DD 128
#define KK 8
#define CC 2000
#define UU 20000
#define NN_MAX 50000
#define QB 148                 // blocks in k_q (1 per SM, 512 threads)
#define CK (CC * KK)           // 16000

typedef unsigned long long ull;

// ---- scratch (device globals; no allocation allowed) ----
__device__ float g_Wc[CC * DD * KK];     // softmax(CA) over D
__device__ float g_A[NN_MAX * KK];       // pooled activity features
__device__ float g_UAs[UU * KK];         // exp(UA) (unnormalized)
__device__ float g_csum[KK];             // col sum of exp(UA)
__device__ float g_Qpart[QB * CK];       // per-block Q partials
__device__ float g_Qs[CK];               // (1 - slide - guess) * Q
__device__ float g_gb[CC];               // guess bias

// ---- f32x2 packed helpers (FFMA2 only reachable via PTX) ----
__device__ __forceinline__ ull pack2(float lo, float hi) {
    ull r;
    asm("mov.b64 %0, {%1, %2};" : "=l"(r) : "f"(lo), "f"(hi));
    return r;
}
__device__ __forceinline__ ull fma2(ull a, ull b, ull c) {
    ull d;
    asm("fma.rn.f32x2 %0, %1, %2, %3;" : "=l"(d) : "l"(a), "l"(b), "l"(c));
    return d;
}
__device__ __forceinline__ ull mul2(ull a, ull b) {
    ull d;
    asm("mul.rn.f32x2 %0, %1, %2;" : "=l"(d) : "l"(a), "l"(b));
    return d;
}
__device__ __forceinline__ void stcs2(float* p, ull a, ull b) {
    asm volatile("st.global.cs.v2.b64 [%0], {%1, %2};" :: "l"(p), "l"(a), "l"(b) : "memory");
}

// ---- 0: zero the UA column sums (must re-zero on every graph replay) ----
__global__ void k_init() {
    if (threadIdx.x < KK) g_csum[threadIdx.x] = 0.f;
}

// ---- 1: colsum of exp(UA)  (no max-shift: UA ~ N(0,1), exp is safe) ----
__global__ void k_ua_sum(const float* __restrict__ UA) {
    int u = blockIdx.x * blockDim.x + threadIdx.x;
    int lane = threadIdx.x & 31;
    float ps[KK];
#pragma unroll
    for (int k = 0; k < KK; k++)
        ps[k] = (u < UU) ? __expf(UA[u * KK + k]) : 0.f;
#pragma unroll
    for (int o = 16; o; o >>= 1)
#pragma unroll
        for (int k = 0; k < KK; k++)
            ps[k] += __shfl_xor_sync(0xffffffffu, ps[k], o);
    if (lane == 0) {
#pragma unroll
        for (int k = 0; k < KK; k++) atomicAdd(&g_csum[k], ps[k]);
    }
}

// ---- 2: g_UAs = exp(UA) (column normalization deferred to k_q epilogue) ----
__global__ void k_uas(const float* __restrict__ UA) {
    int i = blockIdx.x * blockDim.x + threadIdx.x;
    if (i < UU * KK) g_UAs[i] = __expf(UA[i]);
}

// ---- 3: Wc = softmax(CA, axis=D): one block per course, smem-staged coalesced ----
__global__ void k_wc(const float* __restrict__ CA) {
    __shared__ float s[DD * KK];  // 4KB
    int c = blockIdx.x, t = threadIdx.x;  // 256 threads
    const float4* src = (const float4*)(CA + (size_t)c * DD * KK);
    ((float4*)s)[t] = src[t];
    __syncthreads();
    int w = t >> 5, lane = t & 31;  // warp w owns behavior column k=w
    float e[4], sum = 0.f;
#pragma unroll
    for (int j = 0; j < 4; j++) {
        int d = lane + 32 * j;
        e[j] = __expf(s[d * KK + w]);
        sum += e[j];
    }
#pragma unroll
    for (int o = 16; o; o >>= 1) sum += __shfl_xor_sync(0xffffffffu, sum, o);
    float inv = __fdividef(1.f, sum);
#pragma unroll
    for (int j = 0; j < 4; j++) {
        int d = lane + 32 * j;
        s[d * KK + w] = e[j] * inv;
    }
    __syncthreads();
    float4* dst = (float4*)(g_Wc + (size_t)c * DD * KK);
    dst[t] = ((float4*)s)[t];
}

// ---- 4: A[i,k] = sum_d X[i,d] * Wc[cour[i],d,k] : one warp per TWO samples ----
__global__ void k_a(const float* __restrict__ X, const int* __restrict__ cour, int n) {
    int w = blockIdx.x * (blockDim.x >> 5) + (threadIdx.x >> 5);
    int lane = threadIdx.x & 31;
    int i0 = w * 2;
    if (i0 >= n) return;
    bool two = (i0 + 1 < n);
    int i1 = two ? i0 + 1 : i0;
    int ca = __ldg(cour + i0), cb = __ldg(cour + i1);
    const float* xr0 = X + (size_t)i0 * DD;
    const float* xr1 = X + (size_t)i1 * DD;
    float x0[4], x1[4];
#pragma unroll
    for (int j = 0; j < 4; j++) {
        x0[j] = xr0[lane + 32 * j];
        x1[j] = xr1[lane + 32 * j];
    }
    const float* wa = g_Wc + (size_t)ca * DD * KK;
    const float* wb = g_Wc + (size_t)cb * DD * KK;
    float A0[KK], A1[KK];
#pragma unroll
    for (int k = 0; k < KK; k++) { A0[k] = 0.f; A1[k] = 0.f; }
#pragma unroll
    for (int j = 0; j < 4; j++) {
        int d = lane + 32 * j;
        float4 p0 = *(const float4*)(wa + d * KK);
        float4 p1 = *(const float4*)(wa + d * KK + 4);
        float4 q0 = *(const float4*)(wb + d * KK);
        float4 q1 = *(const float4*)(wb + d * KK + 4);
        A0[0] = fmaf(x0[j], p0.x, A0[0]); A0[1] = fmaf(x0[j], p0.y, A0[1]);
        A0[2] = fmaf(x0[j], p0.z, A0[2]); A0[3] = fmaf(x0[j], p0.w, A0[3]);
        A0[4] = fmaf(x0[j], p1.x, A0[4]); A0[5] = fmaf(x0[j], p1.y, A0[5]);
        A0[6] = fmaf(x0[j], p1.z, A0[6]); A0[7] = fmaf(x0[j], p1.w, A0[7]);
        A1[0] = fmaf(x1[j], q0.x, A1[0]); A1[1] = fmaf(x1[j], q0.y, A1[1]);
        A1[2] = fmaf(x1[j], q0.z, A1[2]); A1[3] = fmaf(x1[j], q0.w, A1[3]);
        A1[4] = fmaf(x1[j], q1.x, A1[4]); A1[5] = fmaf(x1[j], q1.y, A1[5]);
        A1[6] = fmaf(x1[j], q1.z, A1[6]); A1[7] = fmaf(x1[j], q1.w, A1[7]);
    }
#pragma unroll
    for (int o = 16; o; o >>= 1)
#pragma unroll
        for (int k = 0; k < KK; k++) {
            A0[k] += __shfl_xor_sync(0xffffffffu, A0[k], o);
            A1[k] += __shfl_xor_sync(0xffffffffu, A1[k], o);
        }
    if (lane == 0) {
        float4* ar = (float4*)(g_A + (size_t)i0 * KK);
        ar[0] = make_float4(A0[0], A0[1], A0[2], A0[3]);
        ar[1] = make_float4(A0[4], A0[5], A0[6], A0[7]);
        if (two) {
            float4* br = (float4*)(g_A + (size_t)i1 * KK);
            br[0] = make_float4(A1[0], A1[1], A1[2], A1[3]);
            br[1] = make_float4(A1[4], A1[5], A1[6], A1[7]);
        }
    }
}

// ---- 5: Q partials. 512 threads x 4 cols, 2 rows per barrier, 2-deep prefetch,
//         packed FFMA2 rank-1 update, UA staged one iteration ahead. ----
__global__ void __launch_bounds__(512, 1) k_q(const float* __restrict__ UC, int rpb) {
    __shared__ float red[2][2][16];
    __shared__ __align__(16) float sua[2][2][8];
    int t = threadIdx.x, lane = t & 31, wid = t >> 5;
    int c0 = t * 4;
    bool act = (c0 < CC);
    ull q[16];  // q[j*4+p] = (Q[c0+j][2p], Q[c0+j][2p+1]) partial
#pragma unroll
    for (int j = 0; j < 16; j++) q[j] = 0ull;

    int u0 = blockIdx.x * rpb;
    int u1 = u0 + rpb; if (u1 > UU) u1 = UU;

    float4 pf0 = make_float4(0, 0, 0, 0), pf1 = pf0;
    if (act && u0 < u1) {
        pf0 = *(const float4*)(UC + (size_t)u0 * CC + c0);
        pf1 = *(const float4*)(UC + (size_t)(u0 + 1) * CC + c0);
    }
    if (t < 16 && u0 < u1) {
        int r = t >> 3, k = t & 7;
        sua[0][r][k] = g_UAs[(size_t)(u0 + r) * KK + k];
    }
    int par = 0;
    for (int u = u0; u < u1; u += 2, par ^= 1) {
        float x0[4] = {pf0.x, pf0.y, pf0.z, pf0.w};
        float x1[4] = {pf1.x, pf1.y, pf1.z, pf1.w};
        if (act && u + 2 < u1) {  // prefetch next row pair
            pf0 = *(const float4*)(UC + (size_t)(u + 2) * CC + c0);
            pf1 = *(const float4*)(UC + (size_t)(u + 3) * CC + c0);
        }
        float e0[4], e1[4], ls0 = 0.f, ls1 = 0.f;
#pragma unroll
        for (int j = 0; j < 4; j++) {
            e0[j] = act ? __expf(x0[j]) : 0.f; ls0 += e0[j];
            e1[j] = act ? __expf(x1[j]) : 0.f; ls1 += e1[j];
        }
#pragma unroll
        for (int o = 16; o; o >>= 1) {
            ls0 += __shfl_xor_sync(0xffffffffu, ls0, o);
            ls1 += __shfl_xor_sync(0xffffffffu, ls1, o);
        }
        if (lane == 0) { red[par][0][wid] = ls0; red[par][1][wid] = ls1; }
        __syncthreads();
        float s0 = 0.f, s1 = 0.f;
#pragma unroll
        for (int w = 0; w < 16; w++) { s0 += red[par][0][w]; s1 += red[par][1][w]; }
        // stage next pair's UA AFTER the barrier (read after the NEXT barrier -> race-free)
        if (t < 16 && u + 2 < u1) {
            int r = t >> 3, k = t & 7;
            sua[par ^ 1][r][k] = g_UAs[(size_t)(u + 2 + r) * KK + k];
        }
        float inv0 = __fdividef(1.f, s0), inv1 = __fdividef(1.f, s1);
        ull i0p = pack2(inv0, inv0), i1p = pack2(inv1, inv1);
        const ull* p0 = (const ull*)sua[par][0];
        const ull* p1 = (const ull*)sua[par][1];
        ull ua0[4], ua1[4];
#pragma unroll
        for (int p = 0; p < 4; p++) {
            ua0[p] = mul2(p0[p], i0p);
            ua1[p] = mul2(p1[p], i1p);
        }
        if (act) {
#pragma unroll
            for (int j = 0; j < 4; j++) {
                ull e0p = pack2(e0[j], e0[j]);
                ull e1p = pack2(e1[j], e1[j]);
#pragma unroll
                for (int p = 0; p < 4; p++) {
                    q[j * 4 + p] = fma2(e0p, ua0[p], q[j * 4 + p]);
                    q[j * 4 + p] = fma2(e1p, ua1[p], q[j * 4 + p]);
                }
            }
        }
    }
    if (act) {
        ull cin[4];
#pragma unroll
        for (int p = 0; p < 4; p++)
            cin[p] = pack2(__fdividef(1.f, g_csum[2 * p]),
                           __fdividef(1.f, g_csum[2 * p + 1]));
        float* dst = g_Qpart + (size_t)blockIdx.x * CK + (size_t)c0 * KK;
#pragma unroll
        for (int j = 0; j < 4; j++) {
            ulonglong2 v0, v1;
            v0.x = mul2(q[j * 4 + 0], cin[0]); v0.y = mul2(q[j * 4 + 1], cin[1]);
            v1.x = mul2(q[j * 4 + 2], cin[2]); v1.y = mul2(q[j * 4 + 3], cin[3]);
            *(ulonglong2*)(dst + j * 8)     = v0;
            *(ulonglong2*)(dst + j * 8 + 4) = v1;
        }
    }
}

// ---- 6: reduce partials (vectorized) + fold sigmoid(guess/slide) ----
__global__ void k_fold(const float* __restrict__ guess_, const float* __restrict__ slide_) {
    int g4 = blockIdx.x * blockDim.x + threadIdx.x;
    if (g4 >= CK / 4) return;
    int i = g4 * 4;
    float4 s = make_float4(0, 0, 0, 0);
#pragma unroll 4
    for (int b = 0; b < QB; b++) {
        float4 v = *(const float4*)(g_Qpart + (size_t)b * CK + i);
        s.x += v.x; s.y += v.y; s.z += v.z; s.w += v.w;
    }
    int c = i >> 3;
    float g  = __fdividef(1.f, 1.f + __expf(-guess_[c]));
    float sl = __fdividef(1.f, 1.f + __expf(-slide_[c]));
    float sc = 1.f - sl - g;
    s.x *= sc; s.y *= sc; s.z *= sc; s.w *= sc;
    *(float4*)(g_Qs + i) = s;
    if ((i & 7) == 0) g_gb[c] = g;
}

// ---- 7: Y[i,c] = gb[c] + A[i,:]·Qs[c,:] ; 8 cols/thread, FFMA2, streaming stores ----
__global__ void __launch_bounds__(256, 2) k_y(float* __restrict__ Y, int rpb, int n) {
    int t = threadIdx.x;
    int c0 = t * 8;
    if (c0 >= CC) return;  // no syncs in this kernel; early exit is safe
    ull q2[32], gb2[4];     // q2[p*8+k] = (Qs[c0+2p][k], Qs[c0+2p+1][k])
    {
        float qs[64];
        const float4* qp = (const float4*)(g_Qs + (size_t)c0 * KK);
#pragma unroll
        for (int j = 0; j < 16; j++) {
            float4 r = qp[j];
            qs[j * 4 + 0] = r.x; qs[j * 4 + 1] = r.y;
            qs[j * 4 + 2] = r.z; qs[j * 4 + 3] = r.w;
        }
#pragma unroll
        for (int p = 0; p < 4; p++)
#pragma unroll
            for (int k = 0; k < 8; k++)
                q2[p * 8 + k] = pack2(qs[(2 * p) * 8 + k], qs[(2 * p + 1) * 8 + k]);
        float4 b0 = *(const float4*)(g_gb + c0);
        float4 b1 = *(const float4*)(g_gb + c0 + 4);
        gb2[0] = pack2(b0.x, b0.y); gb2[1] = pack2(b0.z, b0.w);
        gb2[2] = pack2(b1.x, b1.y); gb2[3] = pack2(b1.z, b1.w);
    }
    int i0 = blockIdx.x * rpb;
    int i1 = i0 + rpb; if (i1 > n) i1 = n;
    for (int i = i0; i < i1; ++i) {
        const float4* ap = (const float4*)(g_A + (size_t)i * KK);
        float4 a0 = ap[0], a1 = ap[1];
        ull apk[8];
        apk[0] = pack2(a0.x, a0.x); apk[1] = pack2(a0.y, a0.y);
        apk[2] = pack2(a0.z, a0.z); apk[3] = pack2(a0.w, a0.w);
        apk[4] = pack2(a1.x, a1.x); apk[5] = pack2(a1.y, a1.y);
        apk[6] = pack2(a1.z, a1.z); apk[7] = pack2(a1.w, a1.w);
        ull acc[4] = {gb2[0], gb2[1], gb2[2], gb2[3]};
#pragma unroll
        for (int k = 0; k < 8; k++)
#pragma unroll
            for (int p = 0; p < 4; p++)
                acc[p] = fma2(apk[k], q2[p * 8 + k], acc[p]);
        float* yp = Y + (size_t)i * CC + c0;
        stcs2(yp,     acc[0], acc[1]);
        stcs2(yp + 4, acc[2], acc[3]);
    }
}

extern "C" void kernel_launch(void* const* d_in, const int* in_sizes, int n_in,
                              void* d_out, int out_size) {
    const float* X      = (const float*)d_in[0];
    const int*   cour   = (const int*)d_in[1];
    const float* CA     = (const float*)d_in[2];
    const float* UA     = (const float*)d_in[3];
    const float* UC     = (const float*)d_in[4];
    const float* guess_ = (const float*)d_in[5];
    const float* slide_ = (const float*)d_in[6];
    float* Y = (float*)d_out;
    int n = in_sizes[1];  // number of samples

    k_init<<<1, 32>>>();
    k_ua_sum<<<(UU + 255) / 256, 256>>>(UA);
    k_uas<<<(UU * KK + 255) / 256, 256>>>(UA);
    k_wc<<<CC, 256>>>(CA);
    int warps = (n + 1) / 2;
    k_a<<<(warps + 7) / 8, 256>>>(X, cour, n);
    int rpb = (UU + QB - 1) / QB;        // 136, even
    k_q<<<QB, 512>>>(UC, rpb);
    k_fold<<<(CK / 4 + 255) / 256, 256>>>(guess_, slide_);
    int yrpb = 32;
    k_y<<<(n + yrpb - 1) / yrpb, 256>>>(Y, yrpb, n);
}

// round 8
// speedup vs baseline: 1.4697x; 1.4697x over previous
#include <cuda_runtime.h>

#define DD 128
#define KK 8
#define CC 2000
#define UU 20000
#define NN_MAX 50000
#define QB 296                 // blocks in k_q (2 per SM on 148 SMs)
#define CK (CC * KK)           // 16000

typedef unsigned long long ull;

// ---- scratch (device globals; no allocation allowed) ----
__device__ float g_Wc[CC * DD * KK];     // softmax(CA) over D
__device__ float g_csum[KK];             // col sum of exp(UA)
__device__ float g_Qpart[QB * CK];       // per-block Q partials
__device__ float g_Qs[CK];               // (1 - slide - guess) * Q
__device__ float g_gb[CC];               // guess bias

// ---- f32x2 packed helpers (FFMA2 only reachable via PTX) ----
__device__ __forceinline__ ull pack2(float lo, float hi) {
    ull r;
    asm("mov.b64 %0, {%1, %2};" : "=l"(r) : "f"(lo), "f"(hi));
    return r;
}
__device__ __forceinline__ ull fma2(ull a, ull b, ull c) {
    ull d;
    asm("fma.rn.f32x2 %0, %1, %2, %3;" : "=l"(d) : "l"(a), "l"(b), "l"(c));
    return d;
}
__device__ __forceinline__ ull mul2(ull a, ull b) {
    ull d;
    asm("mul.rn.f32x2 %0, %1, %2;" : "=l"(d) : "l"(a), "l"(b));
    return d;
}

// ---- 0: zero the UA column sums (must re-zero on every graph replay) ----
__global__ void k_init() {
    if (threadIdx.x < KK) g_csum[threadIdx.x] = 0.f;
}

// ---- 1: colsum of exp(UA)  (no max-shift: UA ~ N(0,1), exp is safe) ----
__global__ void k_ua_sum(const float* __restrict__ UA) {
    int u = blockIdx.x * blockDim.x + threadIdx.x;
    int lane = threadIdx.x & 31;
    float ps[KK];
#pragma unroll
    for (int k = 0; k < KK; k++)
        ps[k] = (u < UU) ? __expf(UA[u * KK + k]) : 0.f;
#pragma unroll
    for (int o = 16; o; o >>= 1)
#pragma unroll
        for (int k = 0; k < KK; k++)
            ps[k] += __shfl_xor_sync(0xffffffffu, ps[k], o);
    if (lane == 0) {
#pragma unroll
        for (int k = 0; k < KK; k++) atomicAdd(&g_csum[k], ps[k]);
    }
}

// ---- 2: Wc = softmax(CA, axis=D): block per course, PADDED smem (stride 9,
//         coprime with 32 banks -> conflict-free column access) ----
__global__ void k_wc(const float* __restrict__ CA) {
    __shared__ float s[DD * 9];   // 4.5KB, row stride 9
    int c = blockIdx.x, t = threadIdx.x;  // 256 threads
    const float4* src = (const float4*)(CA + (size_t)c * DD * KK);
    float4 v = src[t];
    int base = t * 4;             // base%8 is 0 or 4 -> all 4 in same row d
    int d0 = base >> 3, k0 = base & 7;
    float* sp = s + d0 * 9 + k0;
    sp[0] = v.x; sp[1] = v.y; sp[2] = v.z; sp[3] = v.w;
    __syncthreads();
    int w = t >> 5, lane = t & 31;  // warp w owns behavior column k=w
    float e[4], sum = 0.f;
#pragma unroll
    for (int j = 0; j < 4; j++) {
        int d = lane + 32 * j;
        e[j] = __expf(s[d * 9 + w]);
        sum += e[j];
    }
#pragma unroll
    for (int o = 16; o; o >>= 1) sum += __shfl_xor_sync(0xffffffffu, sum, o);
    float inv = __fdividef(1.f, sum);
#pragma unroll
    for (int j = 0; j < 4; j++) {
        int d = lane + 32 * j;
        s[d * 9 + w] = e[j] * inv;
    }
    __syncthreads();
    float4 o4 = make_float4(sp[0], sp[1], sp[2], sp[3]);
    float4* dst = (float4*)(g_Wc + (size_t)c * DD * KK);
    dst[t] = o4;
}

// ---- 3: Q partials. (reverted to the measured-good 243.7us version)
//         256 thr x 8 cols, 1 barrier/row (parity buffers), prefetch,
//         packed FFMA2 rank-1 update, plain partial stores. ----
__global__ void __launch_bounds__(256, 2) k_q(const float* __restrict__ UC,
                                              const float* __restrict__ UA, int rpb) {
    __shared__ float red[2][8];
    __shared__ __align__(8) float sua[2][8];
    int t = threadIdx.x, lane = t & 31, wid = t >> 5;
    int c0 = t * 8;
    bool act = (c0 < CC);
    float invc = 0.f;
    if (t < KK) invc = __fdividef(1.f, g_csum[t]);

    ull q[32];  // q[j*4+p] = (Q[c0+j][2p], Q[c0+j][2p+1]) partial
#pragma unroll
    for (int j = 0; j < 32; j++) q[j] = 0ull;

    int u0 = blockIdx.x * rpb;
    int u1 = u0 + rpb; if (u1 > UU) u1 = UU;

    float4 xa = make_float4(0, 0, 0, 0), xb = make_float4(0, 0, 0, 0);
    if (act && u0 < u1) {
        const float* r = UC + (size_t)u0 * CC + c0;
        xa = *(const float4*)r;
        xb = *(const float4*)(r + 4);
    }
    int parity = 0;
    for (int u = u0; u < u1; ++u, parity ^= 1) {
        float x[8] = {xa.x, xa.y, xa.z, xa.w, xb.x, xb.y, xb.z, xb.w};
        if (act && u + 1 < u1) {  // prefetch next row
            const float* r = UC + (size_t)(u + 1) * CC + c0;
            xa = *(const float4*)r;
            xb = *(const float4*)(r + 4);
        }
        float e[8], ls = 0.f;
#pragma unroll
        for (int j = 0; j < 8; j++) {
            e[j] = act ? __expf(x[j]) : 0.f;
            ls += e[j];
        }
#pragma unroll
        for (int o = 16; o; o >>= 1) ls += __shfl_xor_sync(0xffffffffu, ls, o);
        if (lane == 0) red[parity][wid] = ls;
        if (t < KK) sua[parity][t] = __expf(UA[(size_t)u * KK + t]) * invc;
        __syncthreads();
        float s = red[parity][0];
#pragma unroll
        for (int w = 1; w < 8; w++) s += red[parity][w];
        float inv = __fdividef(1.f, s);
        ull invp = pack2(inv, inv);
        const ull* sp = (const ull*)sua[parity];
        ull uap[4];
#pragma unroll
        for (int p = 0; p < 4; p++) uap[p] = mul2(sp[p], invp);
        if (act) {
#pragma unroll
            for (int j = 0; j < 8; j++) {
                ull ep = pack2(e[j], e[j]);
#pragma unroll
                for (int p = 0; p < 4; p++)
                    q[j * 4 + p] = fma2(ep, uap[p], q[j * 4 + p]);
            }
        }
    }
    if (act) {
        float* dst = g_Qpart + (size_t)blockIdx.x * CK + (size_t)c0 * KK;
#pragma unroll
        for (int j = 0; j < 8; j++) {
            ulonglong2 v0; v0.x = q[j * 4 + 0]; v0.y = q[j * 4 + 1];
            ulonglong2 v1; v1.x = q[j * 4 + 2]; v1.y = q[j * 4 + 3];
            *(ulonglong2*)(dst + j * 8)     = v0;
            *(ulonglong2*)(dst + j * 8 + 4) = v1;
        }
    }
}

// ---- 4: reduce partials (float4) + fold sigmoid(guess/slide) ----
__global__ void k_fold(const float* __restrict__ guess_, const float* __restrict__ slide_) {
    int g4 = blockIdx.x * blockDim.x + threadIdx.x;
    if (g4 >= CK / 4) return;
    int i = g4 * 4;
    float4 s = make_float4(0, 0, 0, 0);
#pragma unroll 4
    for (int b = 0; b < QB; b++) {
        float4 v = *(const float4*)(g_Qpart + (size_t)b * CK + i);
        s.x += v.x; s.y += v.y; s.z += v.z; s.w += v.w;
    }
    int c = i >> 3;
    float g  = __fdividef(1.f, 1.f + __expf(-guess_[c]));
    float sl = __fdividef(1.f, 1.f + __expf(-slide_[c]));
    float sc = 1.f - sl - g;
    s.x *= sc; s.y *= sc; s.z *= sc; s.w *= sc;
    *(float4*)(g_Qs + i) = s;
    if ((i & 7) == 0) g_gb[c] = g;
}

// ---- 5: FUSED A+Y. Phase 1: block computes A for its 32 samples into smem
//         (8 warps x 4 samples, warp-reduce). Phase 2: Y = gb + A.Qs' with
//         Q' cached in registers, packed FFMA2, plain wide stores. ----
__global__ void __launch_bounds__(256, 2) k_y(float* __restrict__ Y,
                                              const float* __restrict__ X,
                                              const int* __restrict__ cour, int n) {
    __shared__ __align__(16) float sA[32 * KK];   // 1KB
    int t = threadIdx.x, w = t >> 5, lane = t & 31;
    int i0 = blockIdx.x * 32;

    // ---- phase 1: A rows for samples i0..i0+31 ----
#pragma unroll 1
    for (int r = 0; r < 4; r++) {
        int li = w * 4 + r;
        int i = i0 + li;
        if (i >= n) break;
        int c = __ldg(cour + i);
        const float* xr = X + (size_t)i * DD;
        const float* wr = g_Wc + (size_t)c * DD * KK;
        float acc[KK];
#pragma unroll
        for (int k = 0; k < KK; k++) acc[k] = 0.f;
#pragma unroll
        for (int j = 0; j < 4; j++) {
            int d = lane + 32 * j;
            float x = xr[d];
            float4 w0 = *(const float4*)(wr + d * KK);
            float4 w1 = *(const float4*)(wr + d * KK + 4);
            acc[0] = fmaf(x, w0.x, acc[0]); acc[1] = fmaf(x, w0.y, acc[1]);
            acc[2] = fmaf(x, w0.z, acc[2]); acc[3] = fmaf(x, w0.w, acc[3]);
            acc[4] = fmaf(x, w1.x, acc[4]); acc[5] = fmaf(x, w1.y, acc[5]);
            acc[6] = fmaf(x, w1.z, acc[6]); acc[7] = fmaf(x, w1.w, acc[7]);
        }
#pragma unroll
        for (int o = 16; o; o >>= 1)
#pragma unroll
            for (int k = 0; k < KK; k++)
                acc[k] += __shfl_xor_sync(0xffffffffu, acc[k], o);
        if (lane == 0) {
            float4* ar = (float4*)(sA + li * KK);
            ar[0] = make_float4(acc[0], acc[1], acc[2], acc[3]);
            ar[1] = make_float4(acc[4], acc[5], acc[6], acc[7]);
        }
    }
    __syncthreads();

    // ---- phase 2: Y rows ----
    int c0 = t * 8;
    if (c0 >= CC) return;
    ull q2[32], gb2[4];     // q2[p*8+k] = (Qs[c0+2p][k], Qs[c0+2p+1][k])
    {
        float qs[64];
        const float4* qp = (const float4*)(g_Qs + (size_t)c0 * KK);
#pragma unroll
        for (int j = 0; j < 16; j++) {
            float4 rr = qp[j];
            qs[j * 4 + 0] = rr.x; qs[j * 4 + 1] = rr.y;
            qs[j * 4 + 2] = rr.z; qs[j * 4 + 3] = rr.w;
        }
#pragma unroll
        for (int p = 0; p < 4; p++)
#pragma unroll
            for (int k = 0; k < 8; k++)
                q2[p * 8 + k] = pack2(qs[(2 * p) * 8 + k], qs[(2 * p + 1) * 8 + k]);
        float4 b0 = *(const float4*)(g_gb + c0);
        float4 b1 = *(const float4*)(g_gb + c0 + 4);
        gb2[0] = pack2(b0.x, b0.y); gb2[1] = pack2(b0.z, b0.w);
        gb2[2] = pack2(b1.x, b1.y); gb2[3] = pack2(b1.z, b1.w);
    }
    int imax = n - i0; if (imax > 32) imax = 32;
    for (int s = 0; s < imax; ++s) {
        const float4* ap = (const float4*)(sA + s * KK);
        float4 a0 = ap[0], a1 = ap[1];  // smem broadcast
        ull apk[8];
        apk[0] = pack2(a0.x, a0.x); apk[1] = pack2(a0.y, a0.y);
        apk[2] = pack2(a0.z, a0.z); apk[3] = pack2(a0.w, a0.w);
        apk[4] = pack2(a1.x, a1.x); apk[5] = pack2(a1.y, a1.y);
        apk[6] = pack2(a1.z, a1.z); apk[7] = pack2(a1.w, a1.w);
        ull acc[4] = {gb2[0], gb2[1], gb2[2], gb2[3]};
#pragma unroll
        for (int k = 0; k < 8; k++)
#pragma unroll
            for (int p = 0; p < 4; p++)
                acc[p] = fma2(apk[k], q2[p * 8 + k], acc[p]);
        float* yp = Y + (size_t)(i0 + s) * CC + c0;
        ulonglong2 s0; s0.x = acc[0]; s0.y = acc[1];
        ulonglong2 s1; s1.x = acc[2]; s1.y = acc[3];
        *(ulonglong2*)(yp)     = s0;
        *(ulonglong2*)(yp + 4) = s1;
    }
}

extern "C" void kernel_launch(void* const* d_in, const int* in_sizes, int n_in,
                              void* d_out, int out_size) {
    const float* X      = (const float*)d_in[0];
    const int*   cour   = (const int*)d_in[1];
    const float* CA     = (const float*)d_in[2];
    const float* UA     = (const float*)d_in[3];
    const float* UC     = (const float*)d_in[4];
    const float* guess_ = (const float*)d_in[5];
    const float* slide_ = (const float*)d_in[6];
    float* Y = (float*)d_out;
    int n = in_sizes[1];  // number of samples

    k_init<<<1, 32>>>();
    k_ua_sum<<<(UU + 255) / 256, 256>>>(UA);
    k_wc<<<CC, 256>>>(CA);
    int rpb = (UU + QB - 1) / QB;
    k_q<<<QB, 256>>>(UC, UA, rpb);
    k_fold<<<(CK / 4 + 255) / 256, 256>>>(guess_, slide_);
    k_y<<<(n + 31) / 32, 256>>>(Y, X, cour, n);
}

// round 9
// speedup vs baseline: 1.6631x; 1.1316x over previous
#include <cuda_runtime.h>

#define DD 128
#define KK 8
#define CC 2000
#define UU 20000
#define NN_MAX 50000
#define QB 296                 // blocks in k_q (2 per SM on 148 SMs)
#define CK (CC * KK)           // 16000

typedef unsigned long long ull;

// ---- scratch (device globals; no allocation allowed) ----
__device__ float g_Wc[CC * DD * KK];     // softmax(CA) over D
__device__ float g_A[NN_MAX * KK];       // pooled activity features
__device__ float g_csum[KK];             // col sum of exp(UA)
__device__ float g_Qpart[QB * CK];       // per-block Q partials
__device__ float g_Qs[CK];               // (1 - slide - guess) * Q
__device__ float g_gb[CC];               // guess bias

// ---- f32x2 packed helpers (FFMA2 only reachable via PTX) ----
__device__ __forceinline__ ull pack2(float lo, float hi) {
    ull r;
    asm("mov.b64 %0, {%1, %2};" : "=l"(r) : "f"(lo), "f"(hi));
    return r;
}
__device__ __forceinline__ ull fma2(ull a, ull b, ull c) {
    ull d;
    asm("fma.rn.f32x2 %0, %1, %2, %3;" : "=l"(d) : "l"(a), "l"(b), "l"(c));
    return d;
}
__device__ __forceinline__ ull mul2(ull a, ull b) {
    ull d;
    asm("mul.rn.f32x2 %0, %1, %2;" : "=l"(d) : "l"(a), "l"(b));
    return d;
}

// ---- 0: zero the UA column sums (must re-zero on every graph replay) ----
__global__ void k_init() {
    if (threadIdx.x < KK) g_csum[threadIdx.x] = 0.f;
}

// ---- 1: colsum of exp(UA)  (no max-shift: UA ~ N(0,1), exp is safe) ----
__global__ void k_ua_sum(const float* __restrict__ UA) {
    int u = blockIdx.x * blockDim.x + threadIdx.x;
    int lane = threadIdx.x & 31;
    float ps[KK];
#pragma unroll
    for (int k = 0; k < KK; k++)
        ps[k] = (u < UU) ? __expf(UA[u * KK + k]) : 0.f;
#pragma unroll
    for (int o = 16; o; o >>= 1)
#pragma unroll
        for (int k = 0; k < KK; k++)
            ps[k] += __shfl_xor_sync(0xffffffffu, ps[k], o);
    if (lane == 0) {
#pragma unroll
        for (int k = 0; k < KK; k++) atomicAdd(&g_csum[k], ps[k]);
    }
}

// ---- 2: Wc = softmax(CA, axis=D): block per course, PADDED smem (stride 9,
//         coprime with 32 banks -> conflict-free column access) ----
__global__ void k_wc(const float* __restrict__ CA) {
    __shared__ float s[DD * 9];   // 4.5KB, row stride 9
    int c = blockIdx.x, t = threadIdx.x;  // 256 threads
    const float4* src = (const float4*)(CA + (size_t)c * DD * KK);
    float4 v = src[t];
    int base = t * 4;             // base%8 is 0 or 4 -> all 4 in same row d
    int d0 = base >> 3, k0 = base & 7;
    float* sp = s + d0 * 9 + k0;
    sp[0] = v.x; sp[1] = v.y; sp[2] = v.z; sp[3] = v.w;
    __syncthreads();
    int w = t >> 5, lane = t & 31;  // warp w owns behavior column k=w
    float e[4], sum = 0.f;
#pragma unroll
    for (int j = 0; j < 4; j++) {
        int d = lane + 32 * j;
        e[j] = __expf(s[d * 9 + w]);
        sum += e[j];
    }
#pragma unroll
    for (int o = 16; o; o >>= 1) sum += __shfl_xor_sync(0xffffffffu, sum, o);
    float inv = __fdividef(1.f, sum);
#pragma unroll
    for (int j = 0; j < 4; j++) {
        int d = lane + 32 * j;
        s[d * 9 + w] = e[j] * inv;
    }
    __syncthreads();
    float4 o4 = make_float4(sp[0], sp[1], sp[2], sp[3]);
    float4* dst = (float4*)(g_Wc + (size_t)c * DD * KK);
    dst[t] = o4;
}

// ---- 3: A[i,k] = sum_d X[i,d] * Wc[cour[i],d,k] : one warp per TWO samples ----
__global__ void k_a(const float* __restrict__ X, const int* __restrict__ cour, int n) {
    int w = blockIdx.x * (blockDim.x >> 5) + (threadIdx.x >> 5);
    int lane = threadIdx.x & 31;
    int i0 = w * 2;
    if (i0 >= n) return;
    bool two = (i0 + 1 < n);
    int i1 = two ? i0 + 1 : i0;
    int ca = __ldg(cour + i0), cb = __ldg(cour + i1);
    const float* xr0 = X + (size_t)i0 * DD;
    const float* xr1 = X + (size_t)i1 * DD;
    float x0[4], x1[4];
#pragma unroll
    for (int j = 0; j < 4; j++) {
        x0[j] = xr0[lane + 32 * j];
        x1[j] = xr1[lane + 32 * j];
    }
    const float* wa = g_Wc + (size_t)ca * DD * KK;
    const float* wb = g_Wc + (size_t)cb * DD * KK;
    float A0[KK], A1[KK];
#pragma unroll
    for (int k = 0; k < KK; k++) { A0[k] = 0.f; A1[k] = 0.f; }
#pragma unroll
    for (int j = 0; j < 4; j++) {
        int d = lane + 32 * j;
        float4 p0 = *(const float4*)(wa + d * KK);
        float4 p1 = *(const float4*)(wa + d * KK + 4);
        float4 q0 = *(const float4*)(wb + d * KK);
        float4 q1 = *(const float4*)(wb + d * KK + 4);
        A0[0] = fmaf(x0[j], p0.x, A0[0]); A0[1] = fmaf(x0[j], p0.y, A0[1]);
        A0[2] = fmaf(x0[j], p0.z, A0[2]); A0[3] = fmaf(x0[j], p0.w, A0[3]);
        A0[4] = fmaf(x0[j], p1.x, A0[4]); A0[5] = fmaf(x0[j], p1.y, A0[5]);
        A0[6] = fmaf(x0[j], p1.z, A0[6]); A0[7] = fmaf(x0[j], p1.w, A0[7]);
        A1[0] = fmaf(x1[j], q0.x, A1[0]); A1[1] = fmaf(x1[j], q0.y, A1[1]);
        A1[2] = fmaf(x1[j], q0.z, A1[2]); A1[3] = fmaf(x1[j], q0.w, A1[3]);
        A1[4] = fmaf(x1[j], q1.x, A1[4]); A1[5] = fmaf(x1[j], q1.y, A1[5]);
        A1[6] = fmaf(x1[j], q1.z, A1[6]); A1[7] = fmaf(x1[j], q1.w, A1[7]);
    }
#pragma unroll
    for (int o = 16; o; o >>= 1)
#pragma unroll
        for (int k = 0; k < KK; k++) {
            A0[k] += __shfl_xor_sync(0xffffffffu, A0[k], o);
            A1[k] += __shfl_xor_sync(0xffffffffu, A1[k], o);
        }
    if (lane == 0) {
        float4* ar = (float4*)(g_A + (size_t)i0 * KK);
        ar[0] = make_float4(A0[0], A0[1], A0[2], A0[3]);
        ar[1] = make_float4(A0[4], A0[5], A0[6], A0[7]);
        if (two) {
            float4* br = (float4*)(g_A + (size_t)i1 * KK);
            br[0] = make_float4(A1[0], A1[1], A1[2], A1[3]);
            br[1] = make_float4(A1[4], A1[5], A1[6], A1[7]);
        }
    }
}

// ---- 4: Q partials (measured 57us; unchanged this round) ----
__global__ void __launch_bounds__(256, 2) k_q(const float* __restrict__ UC,
                                              const float* __restrict__ UA, int rpb) {
    __shared__ float red[2][8];
    __shared__ __align__(8) float sua[2][8];
    int t = threadIdx.x, lane = t & 31, wid = t >> 5;
    int c0 = t * 8;
    bool act = (c0 < CC);
    float invc = 0.f;
    if (t < KK) invc = __fdividef(1.f, g_csum[t]);

    ull q[32];  // q[j*4+p] = (Q[c0+j][2p], Q[c0+j][2p+1]) partial
#pragma unroll
    for (int j = 0; j < 32; j++) q[j] = 0ull;

    int u0 = blockIdx.x * rpb;
    int u1 = u0 + rpb; if (u1 > UU) u1 = UU;

    float4 xa = make_float4(0, 0, 0, 0), xb = make_float4(0, 0, 0, 0);
    if (act && u0 < u1) {
        const float* r = UC + (size_t)u0 * CC + c0;
        xa = *(const float4*)r;
        xb = *(const float4*)(r + 4);
    }
    int parity = 0;
    for (int u = u0; u < u1; ++u, parity ^= 1) {
        float x[8] = {xa.x, xa.y, xa.z, xa.w, xb.x, xb.y, xb.z, xb.w};
        if (act && u + 1 < u1) {  // prefetch next row
            const float* r = UC + (size_t)(u + 1) * CC + c0;
            xa = *(const float4*)r;
            xb = *(const float4*)(r + 4);
        }
        float e[8], ls = 0.f;
#pragma unroll
        for (int j = 0; j < 8; j++) {
            e[j] = act ? __expf(x[j]) : 0.f;
            ls += e[j];
        }
#pragma unroll
        for (int o = 16; o; o >>= 1) ls += __shfl_xor_sync(0xffffffffu, ls, o);
        if (lane == 0) red[parity][wid] = ls;
        if (t < KK) sua[parity][t] = __expf(UA[(size_t)u * KK + t]) * invc;
        __syncthreads();
        float s = red[parity][0];
#pragma unroll
        for (int w = 1; w < 8; w++) s += red[parity][w];
        float inv = __fdividef(1.f, s);
        ull invp = pack2(inv, inv);
        const ull* sp = (const ull*)sua[parity];
        ull uap[4];
#pragma unroll
        for (int p = 0; p < 4; p++) uap[p] = mul2(sp[p], invp);
        if (act) {
#pragma unroll
            for (int j = 0; j < 8; j++) {
                ull ep = pack2(e[j], e[j]);
#pragma unroll
                for (int p = 0; p < 4; p++)
                    q[j * 4 + p] = fma2(ep, uap[p], q[j * 4 + p]);
            }
        }
    }
    if (act) {
        float* dst = g_Qpart + (size_t)blockIdx.x * CK + (size_t)c0 * KK;
#pragma unroll
        for (int j = 0; j < 8; j++) {
            ulonglong2 v0; v0.x = q[j * 4 + 0]; v0.y = q[j * 4 + 1];
            ulonglong2 v1; v1.x = q[j * 4 + 2]; v1.y = q[j * 4 + 3];
            *(ulonglong2*)(dst + j * 8)     = v0;
            *(ulonglong2*)(dst + j * 8 + 4) = v1;
        }
    }
}

// ---- 5: reduce partials (float4) + fold sigmoid(guess/slide) ----
__global__ void k_fold(const float* __restrict__ guess_, const float* __restrict__ slide_) {
    int g4 = blockIdx.x * blockDim.x + threadIdx.x;
    if (g4 >= CK / 4) return;
    int i = g4 * 4;
    float4 s = make_float4(0, 0, 0, 0);
#pragma unroll 4
    for (int b = 0; b < QB; b++) {
        float4 v = *(const float4*)(g_Qpart + (size_t)b * CK + i);
        s.x += v.x; s.y += v.y; s.z += v.z; s.w += v.w;
    }
    int c = i >> 3;
    float g  = __fdividef(1.f, 1.f + __expf(-guess_[c]));
    float sl = __fdividef(1.f, 1.f + __expf(-slide_[c]));
    float sc = 1.f - sl - g;
    s.x *= sc; s.y *= sc; s.z *= sc; s.w *= sc;
    *(float4*)(g_Qs + i) = s;
    if ((i & 7) == 0) g_gb[c] = g;
}

// ---- 6: Y[i,c] = gb[c] + A[i,:]·Qs[c,:]
//         4 cols/thread, columns split over gridDim.y=2 -> ~70 regs ->
//         3 blocks/SM (24 warps) for store-latency hiding. One STG.128/row. ----
__global__ void __launch_bounds__(256, 3) k_y(float* __restrict__ Y, int rpb, int n) {
    int t = threadIdx.x;
    int c0 = blockIdx.y * 1024 + t * 4;
    if (c0 >= CC) return;  // no syncs in this kernel; early exit is safe
    ull q2[16], gb2[2];    // q2[p*8+k] = (Qs[c0+2p][k], Qs[c0+2p+1][k])
    {
        float qs[32];
        const float4* qp = (const float4*)(g_Qs + (size_t)c0 * KK);
#pragma unroll
        for (int j = 0; j < 8; j++) {
            float4 r = qp[j];
            qs[j * 4 + 0] = r.x; qs[j * 4 + 1] = r.y;
            qs[j * 4 + 2] = r.z; qs[j * 4 + 3] = r.w;
        }
#pragma unroll
        for (int p = 0; p < 2; p++)
#pragma unroll
            for (int k = 0; k < 8; k++)
                q2[p * 8 + k] = pack2(qs[(2 * p) * 8 + k], qs[(2 * p + 1) * 8 + k]);
        float4 b = *(const float4*)(g_gb + c0);
        gb2[0] = pack2(b.x, b.y); gb2[1] = pack2(b.z, b.w);
    }
    int i0 = blockIdx.x * rpb;
    int i1 = i0 + rpb; if (i1 > n) i1 = n;
    for (int i = i0; i < i1; ++i) {
        const float4* ap = (const float4*)(g_A + (size_t)i * KK);
        float4 a0 = ap[0], a1 = ap[1];   // warp-uniform -> LDG broadcast
        ull apk[8];
        apk[0] = pack2(a0.x, a0.x); apk[1] = pack2(a0.y, a0.y);
        apk[2] = pack2(a0.z, a0.z); apk[3] = pack2(a0.w, a0.w);
        apk[4] = pack2(a1.x, a1.x); apk[5] = pack2(a1.y, a1.y);
        apk[6] = pack2(a1.z, a1.z); apk[7] = pack2(a1.w, a1.w);
        ull acc0 = gb2[0], acc1 = gb2[1];
#pragma unroll
        for (int k = 0; k < 8; k++) {
            acc0 = fma2(apk[k], q2[k],     acc0);
            acc1 = fma2(apk[k], q2[8 + k], acc1);
        }
        ulonglong2 s; s.x = acc0; s.y = acc1;
        *(ulonglong2*)(Y + (size_t)i * CC + c0) = s;
    }
}

extern "C" void kernel_launch(void* const* d_in, const int* in_sizes, int n_in,
                              void* d_out, int out_size) {
    const float* X      = (const float*)d_in[0];
    const int*   cour   = (const int*)d_in[1];
    const float* CA     = (const float*)d_in[2];
    const float* UA     = (const float*)d_in[3];
    const float* UC     = (const float*)d_in[4];
    const float* guess_ = (const float*)d_in[5];
    const float* slide_ = (const float*)d_in[6];
    float* Y = (float*)d_out;
    int n = in_sizes[1];  // number of samples

    k_init<<<1, 32>>>();
    k_ua_sum<<<(UU + 255) / 256, 256>>>(UA);
    k_wc<<<CC, 256>>>(CA);
    int warps = (n + 1) / 2;
    k_a<<<(warps + 7) / 8, 256>>>(X, cour, n);
    int rpb = (UU + QB - 1) / QB;
    k_q<<<QB, 256>>>(UC, UA, rpb);
    k_fold<<<(CK / 4 + 255) / 256, 256>>>(guess_, slide_);
    int yrpb = 64;
    dim3 ygrid((n + yrpb - 1) / yrpb, 2);
    k_y<<<ygrid, 256>>>(Y, yrpb, n);
}

// round 11
// speedup vs baseline: 1.7642x; 1.0608x over previous
#include <cuda_runtime.h>

#define DD 128
#define KK 8
#define CC 2000
#define UU 20000
#define NN_MAX 50000
#define QB 296                 // blocks in k_q (2 per SM on 148 SMs)
#define CK (CC * KK)           // 16000
#define UASB 79                // k_ua_sum blocks = ceil(20000/256)

typedef unsigned long long ull;

// ---- scratch (device globals; no allocation allowed) ----
__device__ float g_Wc[CC * DD * KK];     // softmax(CA) over D
__device__ float g_A[NN_MAX * KK];       // pooled activity features
__device__ float g_csum_part[UASB * KK]; // per-block colsum(exp(UA)) partials
__device__ float g_Qpart[QB * CK];       // per-block Q partials
__device__ float g_Qs[CK];               // (1 - slide - guess) * Q / csum
__device__ float g_gb[CC];               // guess bias

// ---- f32x2 packed helpers (FFMA2 only reachable via PTX) ----
__device__ __forceinline__ ull pack2(float lo, float hi) {
    ull r;
    asm("mov.b64 %0, {%1, %2};" : "=l"(r) : "f"(lo), "f"(hi));
    return r;
}
__device__ __forceinline__ ull fma2(ull a, ull b, ull c) {
    ull d;
    asm("fma.rn.f32x2 %0, %1, %2, %3;" : "=l"(d) : "l"(a), "l"(b), "l"(c));
    return d;
}
__device__ __forceinline__ ull mul2(ull a, ull b) {
    ull d;
    asm("mul.rn.f32x2 %0, %1, %2;" : "=l"(d) : "l"(a), "l"(b));
    return d;
}

// ---- 1: per-block colsum of exp(UA) partials (no init, no atomics) ----
__global__ void k_ua_sum(const float* __restrict__ UA) {
    __shared__ float sm[8 * KK];
    int t = threadIdx.x, lane = t & 31, wid = t >> 5;
    int u = blockIdx.x * blockDim.x + t;
    float ps[KK];
#pragma unroll
    for (int k = 0; k < KK; k++)
        ps[k] = (u < UU) ? __expf(UA[u * KK + k]) : 0.f;
#pragma unroll
    for (int o = 16; o; o >>= 1)
#pragma unroll
        for (int k = 0; k < KK; k++)
            ps[k] += __shfl_xor_sync(0xffffffffu, ps[k], o);
    if (lane == 0)
#pragma unroll
        for (int k = 0; k < KK; k++) sm[wid * KK + k] = ps[k];
    __syncthreads();
    if (t < KK) {
        float s = sm[t];
#pragma unroll
        for (int w = 1; w < 8; w++) s += sm[w * KK + t];
        g_csum_part[blockIdx.x * KK + t] = s;
    }
}

// ---- 2: Wc = softmax(CA, axis=D): block per course, PADDED smem (stride 9,
//         coprime with 32 banks -> conflict-free column access) ----
__global__ void k_wc(const float* __restrict__ CA) {
    __shared__ float s[DD * 9];   // 4.5KB, row stride 9
    int c = blockIdx.x, t = threadIdx.x;  // 256 threads
    const float4* src = (const float4*)(CA + (size_t)c * DD * KK);
    float4 v = src[t];
    int base = t * 4;             // base%8 is 0 or 4 -> all 4 in same row d
    int d0 = base >> 3, k0 = base & 7;
    float* sp = s + d0 * 9 + k0;
    sp[0] = v.x; sp[1] = v.y; sp[2] = v.z; sp[3] = v.w;
    __syncthreads();
    int w = t >> 5, lane = t & 31;  // warp w owns behavior column k=w
    float e[4], sum = 0.f;
#pragma unroll
    for (int j = 0; j < 4; j++) {
        int d = lane + 32 * j;
        e[j] = __expf(s[d * 9 + w]);
        sum += e[j];
    }
#pragma unroll
    for (int o = 16; o; o >>= 1) sum += __shfl_xor_sync(0xffffffffu, sum, o);
    float inv = __fdividef(1.f, sum);
#pragma unroll
    for (int j = 0; j < 4; j++) {
        int d = lane + 32 * j;
        s[d * 9 + w] = e[j] * inv;
    }
    __syncthreads();
    float4 o4 = make_float4(sp[0], sp[1], sp[2], sp[3]);
    float4* dst = (float4*)(g_Wc + (size_t)c * DD * KK);
    dst[t] = o4;
}

// ---- 3: A[i,k] = sum_d X[i,d] * Wc[cour[i],d,k] : one warp per TWO samples ----
__global__ void k_a(const float* __restrict__ X, const int* __restrict__ cour, int n) {
    int w = blockIdx.x * (blockDim.x >> 5) + (threadIdx.x >> 5);
    int lane = threadIdx.x & 31;
    int i0 = w * 2;
    if (i0 >= n) return;
    bool two = (i0 + 1 < n);
    int i1 = two ? i0 + 1 : i0;
    int ca = __ldg(cour + i0), cb = __ldg(cour + i1);
    const float* xr0 = X + (size_t)i0 * DD;
    const float* xr1 = X + (size_t)i1 * DD;
    float x0[4], x1[4];
#pragma unroll
    for (int j = 0; j < 4; j++) {
        x0[j] = xr0[lane + 32 * j];
        x1[j] = xr1[lane + 32 * j];
    }
    const float* wa = g_Wc + (size_t)ca * DD * KK;
    const float* wb = g_Wc + (size_t)cb * DD * KK;
    float A0[KK], A1[KK];
#pragma unroll
    for (int k = 0; k < KK; k++) { A0[k] = 0.f; A1[k] = 0.f; }
#pragma unroll
    for (int j = 0; j < 4; j++) {
        int d = lane + 32 * j;
        float4 p0 = *(const float4*)(wa + d * KK);
        float4 p1 = *(const float4*)(wa + d * KK + 4);
        float4 q0 = *(const float4*)(wb + d * KK);
        float4 q1 = *(const float4*)(wb + d * KK + 4);
        A0[0] = fmaf(x0[j], p0.x, A0[0]); A0[1] = fmaf(x0[j], p0.y, A0[1]);
        A0[2] = fmaf(x0[j], p0.z, A0[2]); A0[3] = fmaf(x0[j], p0.w, A0[3]);
        A0[4] = fmaf(x0[j], p1.x, A0[4]); A0[5] = fmaf(x0[j], p1.y, A0[5]);
        A0[6] = fmaf(x0[j], p1.z, A0[6]); A0[7] = fmaf(x0[j], p1.w, A0[7]);
        A1[0] = fmaf(x1[j], q0.x, A1[0]); A1[1] = fmaf(x1[j], q0.y, A1[1]);
        A1[2] = fmaf(x1[j], q0.z, A1[2]); A1[3] = fmaf(x1[j], q0.w, A1[3]);
        A1[4] = fmaf(x1[j], q1.x, A1[4]); A1[5] = fmaf(x1[j], q1.y, A1[5]);
        A1[6] = fmaf(x1[j], q1.z, A1[6]); A1[7] = fmaf(x1[j], q1.w, A1[7]);
    }
#pragma unroll
    for (int o = 16; o; o >>= 1)
#pragma unroll
        for (int k = 0; k < KK; k++) {
            A0[k] += __shfl_xor_sync(0xffffffffu, A0[k], o);
            A1[k] += __shfl_xor_sync(0xffffffffu, A1[k], o);
        }
    if (lane == 0) {
        float4* ar = (float4*)(g_A + (size_t)i0 * KK);
        ar[0] = make_float4(A0[0], A0[1], A0[2], A0[3]);
        ar[1] = make_float4(A0[4], A0[5], A0[6], A0[7]);
        if (two) {
            float4* br = (float4*)(g_A + (size_t)i1 * KK);
            br[0] = make_float4(A1[0], A1[1], A1[2], A1[3]);
            br[1] = make_float4(A1[4], A1[5], A1[6], A1[7]);
        }
    }
}

// ---- 4: Q partials (measured 57us; csum factored out -> no init dependency) ----
__global__ void __launch_bounds__(256, 2) k_q(const float* __restrict__ UC,
                                              const float* __restrict__ UA, int rpb) {
    __shared__ float red[2][8];
    __shared__ __align__(8) float sua[2][8];
    int t = threadIdx.x, lane = t & 31, wid = t >> 5;
    int c0 = t * 8;
    bool act = (c0 < CC);

    ull q[32];  // q[j*4+p] = (Q[c0+j][2p], Q[c0+j][2p+1]) partial
#pragma unroll
    for (int j = 0; j < 32; j++) q[j] = 0ull;

    int u0 = blockIdx.x * rpb;
    int u1 = u0 + rpb; if (u1 > UU) u1 = UU;

    float4 xa = make_float4(0, 0, 0, 0), xb = make_float4(0, 0, 0, 0);
    if (act && u0 < u1) {
        const float* r = UC + (size_t)u0 * CC + c0;
        xa = *(const float4*)r;
        xb = *(const float4*)(r + 4);
    }
    int parity = 0;
    for (int u = u0; u < u1; ++u, parity ^= 1) {
        float x[8] = {xa.x, xa.y, xa.z, xa.w, xb.x, xb.y, xb.z, xb.w};
        if (act && u + 1 < u1) {  // prefetch next row
            const float* r = UC + (size_t)(u + 1) * CC + c0;
            xa = *(const float4*)r;
            xb = *(const float4*)(r + 4);
        }
        float e[8], ls = 0.f;
#pragma unroll
        for (int j = 0; j < 8; j++) {
            e[j] = act ? __expf(x[j]) : 0.f;
            ls += e[j];
        }
#pragma unroll
        for (int o = 16; o; o >>= 1) ls += __shfl_xor_sync(0xffffffffu, ls, o);
        if (lane == 0) red[parity][wid] = ls;
        if (t < KK) sua[parity][t] = __expf(UA[(size_t)u * KK + t]);
        __syncthreads();
        float s = red[parity][0];
#pragma unroll
        for (int w = 1; w < 8; w++) s += red[parity][w];
        float inv = __fdividef(1.f, s);
        ull invp = pack2(inv, inv);
        const ull* sp = (const ull*)sua[parity];
        ull uap[4];
#pragma unroll
        for (int p = 0; p < 4; p++) uap[p] = mul2(sp[p], invp);
        if (act) {
#pragma unroll
            for (int j = 0; j < 8; j++) {
                ull ep = pack2(e[j], e[j]);
#pragma unroll
                for (int p = 0; p < 4; p++)
                    q[j * 4 + p] = fma2(ep, uap[p], q[j * 4 + p]);
            }
        }
    }
    if (act) {
        float* dst = g_Qpart + (size_t)blockIdx.x * CK + (size_t)c0 * KK;
#pragma unroll
        for (int j = 0; j < 8; j++) {
            ulonglong2 v0; v0.x = q[j * 4 + 0]; v0.y = q[j * 4 + 1];
            ulonglong2 v1; v1.x = q[j * 4 + 2]; v1.y = q[j * 4 + 3];
            *(ulonglong2*)(dst + j * 8)     = v0;
            *(ulonglong2*)(dst + j * 8 + 4) = v1;
        }
    }
}

// ---- 5: reduce partials (float4) + csum normalization + sigmoid fold ----
__global__ void k_fold(const float* __restrict__ guess_, const float* __restrict__ slide_) {
    __shared__ float sinv[KK];
    if (threadIdx.x < KK) {
        float s = 0.f;
        for (int b = 0; b < UASB; b++) s += g_csum_part[b * KK + threadIdx.x];
        sinv[threadIdx.x] = __fdividef(1.f, s);
    }
    __syncthreads();
    int g4 = blockIdx.x * blockDim.x + threadIdx.x;
    if (g4 >= CK / 4) return;
    int i = g4 * 4;
    float4 s = make_float4(0, 0, 0, 0);
#pragma unroll 4
    for (int b = 0; b < QB; b++) {
        float4 v = *(const float4*)(g_Qpart + (size_t)b * CK + i);
        s.x += v.x; s.y += v.y; s.z += v.z; s.w += v.w;
    }
    int c = i >> 3, k = i & 7;   // k is 0 or 4
    float g  = __fdividef(1.f, 1.f + __expf(-guess_[c]));
    float sl = __fdividef(1.f, 1.f + __expf(-slide_[c]));
    float sc = 1.f - sl - g;
    s.x *= sc * sinv[k];     s.y *= sc * sinv[k + 1];
    s.z *= sc * sinv[k + 2]; s.w *= sc * sinv[k + 3];
    *(float4*)(g_Qs + i) = s;
    if (k == 0) g_gb[c] = g;
}

// ---- 6: Y[i,c] = gb[c] + A[i,:]·Qs[c,:]
//         4 cols/thread, gridDim.y=2 column split, 3 blocks/SM.
//         Software-pipelined 2-row batches: next pair's A prefetched into
//         registers before computing current pair -> load latency off the path. ----
__global__ void __launch_bounds__(256, 3) k_y(float* __restrict__ Y, int rpb, int n) {
    int t = threadIdx.x;
    int c0 = blockIdx.y * 1024 + t * 4;
    if (c0 >= CC) return;  // no syncs in this kernel; early exit is safe
    ull q2[16], gb2[2];    // q2[p*8+k] = (Qs[c0+2p][k], Qs[c0+2p+1][k])
    {
        float qs[32];
        const float4* qp = (const float4*)(g_Qs + (size_t)c0 * KK);
#pragma unroll
        for (int j = 0; j < 8; j++) {
            float4 r = qp[j];
            qs[j * 4 + 0] = r.x; qs[j * 4 + 1] = r.y;
            qs[j * 4 + 2] = r.z; qs[j * 4 + 3] = r.w;
        }
#pragma unroll
        for (int p = 0; p < 2; p++)
#pragma unroll
            for (int k = 0; k < 8; k++)
                q2[p * 8 + k] = pack2(qs[(2 * p) * 8 + k], qs[(2 * p + 1) * 8 + k]);
        float4 b = *(const float4*)(g_gb + c0);
        gb2[0] = pack2(b.x, b.y); gb2[1] = pack2(b.z, b.w);
    }
    int i0 = blockIdx.x * rpb;
    int i1 = i0 + rpb; if (i1 > n) i1 = n;
    if (i0 >= i1) return;

    // prefetch first pair (clamped indices keep reads in-bounds)
    int ra = i0, rb = (i0 + 1 < i1) ? i0 + 1 : i1 - 1;
    const float4* pa = (const float4*)(g_A + (size_t)ra * KK);
    const float4* pb = (const float4*)(g_A + (size_t)rb * KK);
    float4 a00 = pa[0], a01 = pa[1], a10 = pb[0], a11 = pb[1];

    int i = i0;
    for (; i + 2 <= i1; i += 2) {
        float4 c00 = a00, c01 = a01, c10 = a10, c11 = a11;
        {   // prefetch next pair
            int na = (i + 2 < i1) ? i + 2 : i1 - 1;
            int nb = (i + 3 < i1) ? i + 3 : i1 - 1;
            const float4* qa = (const float4*)(g_A + (size_t)na * KK);
            const float4* qb = (const float4*)(g_A + (size_t)nb * KK);
            a00 = qa[0]; a01 = qa[1]; a10 = qb[0]; a11 = qb[1];
        }
        // row i
        {
            ull acc0 = gb2[0], acc1 = gb2[1], ap;
            ap = pack2(c00.x, c00.x); acc0 = fma2(ap, q2[0], acc0); acc1 = fma2(ap, q2[8],  acc1);
            ap = pack2(c00.y, c00.y); acc0 = fma2(ap, q2[1], acc0); acc1 = fma2(ap, q2[9],  acc1);
            ap = pack2(c00.z, c00.z); acc0 = fma2(ap, q2[2], acc0); acc1 = fma2(ap, q2[10], acc1);
            ap = pack2(c00.w, c00.w); acc0 = fma2(ap, q2[3], acc0); acc1 = fma2(ap, q2[11], acc1);
            ap = pack2(c01.x, c01.x); acc0 = fma2(ap, q2[4], acc0); acc1 = fma2(ap, q2[12], acc1);
            ap = pack2(c01.y, c01.y); acc0 = fma2(ap, q2[5], acc0); acc1 = fma2(ap, q2[13], acc1);
            ap = pack2(c01.z, c01.z); acc0 = fma2(ap, q2[6], acc0); acc1 = fma2(ap, q2[14], acc1);
            ap = pack2(c01.w, c01.w); acc0 = fma2(ap, q2[7], acc0); acc1 = fma2(ap, q2[15], acc1);
            ulonglong2 s; s.x = acc0; s.y = acc1;
            *(ulonglong2*)(Y + (size_t)i * CC + c0) = s;
        }
        // row i+1
        {
            ull acc0 = gb2[0], acc1 = gb2[1], ap;
            ap = pack2(c10.x, c10.x); acc0 = fma2(ap, q2[0], acc0); acc1 = fma2(ap, q2[8],  acc1);
            ap = pack2(c10.y, c10.y); acc0 = fma2(ap, q2[1], acc0); acc1 = fma2(ap, q2[9],  acc1);
            ap = pack2(c10.z, c10.z); acc0 = fma2(ap, q2[2], acc0); acc1 = fma2(ap, q2[10], acc1);
            ap = pack2(c10.w, c10.w); acc0 = fma2(ap, q2[3], acc0); acc1 = fma2(ap, q2[11], acc1);
            ap = pack2(c11.x, c11.x); acc0 = fma2(ap, q2[4], acc0); acc1 = fma2(ap, q2[12], acc1);
            ap = pack2(c11.y, c11.y); acc0 = fma2(ap, q2[5], acc0); acc1 = fma2(ap, q2[13], acc1);
            ap = pack2(c11.z, c11.z); acc0 = fma2(ap, q2[6], acc0); acc1 = fma2(ap, q2[14], acc1);
            ap = pack2(c11.w, c11.w); acc0 = fma2(ap, q2[7], acc0); acc1 = fma2(ap, q2[15], acc1);
            ulonglong2 s; s.x = acc0; s.y = acc1;
            *(ulonglong2*)(Y + (size_t)(i + 1) * CC + c0) = s;
        }
    }
    if (i < i1) {  // odd tail: a00/a01 hold row i (rb clamped to it if pair of one)
        const float4* ap4 = (const float4*)(g_A + (size_t)i * KK);
        float4 c00 = ap4[0], c01 = ap4[1];
        ull acc0 = gb2[0], acc1 = gb2[1], ap;
        ap = pack2(c00.x, c00.x); acc0 = fma2(ap, q2[0], acc0); acc1 = fma2(ap, q2[8],  acc1);
        ap = pack2(c00.y, c00.y); acc0 = fma2(ap, q2[1], acc0); acc1 = fma2(ap, q2[9],  acc1);
        ap = pack2(c00.z, c00.z); acc0 = fma2(ap, q2[2], acc0); acc1 = fma2(ap, q2[10], acc1);
        ap = pack2(c00.w, c00.w); acc0 = fma2(ap, q2[3], acc0); acc1 = fma2(ap, q2[11], acc1);
        ap = pack2(c01.x, c01.x); acc0 = fma2(ap, q2[4], acc0); acc1 = fma2(ap, q2[12], acc1);
        ap = pack2(c01.y, c01.y); acc0 = fma2(ap, q2[5], acc0); acc1 = fma2(ap, q2[13], acc1);
        ap = pack2(c01.z, c01.z); acc0 = fma2(ap, q2[6], acc0); acc1 = fma2(ap, q2[14], acc1);
        ap = pack2(c01.w, c01.w); acc0 = fma2(ap, q2[7], acc0); acc1 = fma2(ap, q2[15], acc1);
        ulonglong2 s; s.x = acc0; s.y = acc1;
        *(ulonglong2*)(Y + (size_t)i * CC + c0) = s;
    }
}

extern "C" void kernel_launch(void* const* d_in, const int* in_sizes, int n_in,
                              void* d_out, int out_size) {
    const float* X      = (const float*)d_in[0];
    const int*   cour   = (const int*)d_in[1];
    const float* CA     = (const float*)d_in[2];
    const float* UA     = (const float*)d_in[3];
    const float* UC     = (const float*)d_in[4];
    const float* guess_ = (const float*)d_in[5];
    const float* slide_ = (const float*)d_in[6];
    float* Y = (float*)d_out;
    int n = in_sizes[1];  // number of samples

    k_ua_sum<<<UASB, 256>>>(UA);
    k_wc<<<CC, 256>>>(CA);
    int warps = (n + 1) / 2;
    k_a<<<(warps + 7) / 8, 256>>>(X, cour, n);
    int rpb = (UU + QB - 1) / QB;
    k_q<<<QB, 256>>>(UC, UA, rpb);
    k_fold<<<(CK / 4 + 255) / 256, 256>>>(guess_, slide_);
    int yrpb = 64;
    dim3 ygrid((n + yrpb - 1) / yrpb, 2);
    k_y<<<ygrid, 256>>>(Y, yrpb, n);
}

// round 15
// speedup vs baseline: 1.8665x; 1.0580x over previous
#include <cuda_runtime.h>

#define DD 128
#define KK 8
#define CC 2000
#define UU 20000
#define NN_MAX 50000
#define QB 296                 // blocks in k_q (2 per SM on 148 SMs)
#define CK (CC * KK)           // 16000
#define UASB 79                // k_ua_sum blocks = ceil(20000/256)

typedef unsigned long long ull;

// ---- scratch (device globals; no allocation allowed) ----
__device__ float g_Wc[CC * DD * KK];     // softmax(CA) over D
__device__ float g_A[NN_MAX * KK];       // pooled activity features
__device__ float g_csum_part[UASB * KK]; // per-block colsum(exp(UA)) partials
__device__ float g_Qpart[QB * CK];       // per-block Q partials
__device__ float g_Qs[CK];               // (1 - slide - guess) * Q / csum
__device__ float g_gb[CC];               // guess bias

// ---- f32x2 packed helpers (FFMA2 only reachable via PTX) ----
__device__ __forceinline__ ull pack2(float lo, float hi) {
    ull r;
    asm("mov.b64 %0, {%1, %2};" : "=l"(r) : "f"(lo), "f"(hi));
    return r;
}
__device__ __forceinline__ ull fma2(ull a, ull b, ull c) {
    ull d;
    asm("fma.rn.f32x2 %0, %1, %2, %3;" : "=l"(d) : "l"(a), "l"(b), "l"(c));
    return d;
}
__device__ __forceinline__ ull mul2(ull a, ull b) {
    ull d;
    asm("mul.rn.f32x2 %0, %1, %2;" : "=l"(d) : "l"(a), "l"(b));
    return d;
}

// ---- 1: per-block colsum of exp(UA) partials (no init, no atomics) ----
__global__ void k_ua_sum(const float* __restrict__ UA) {
    __shared__ float sm[8 * KK];
    int t = threadIdx.x, lane = t & 31, wid = t >> 5;
    int u = blockIdx.x * blockDim.x + t;
    float ps[KK];
#pragma unroll
    for (int k = 0; k < KK; k++)
        ps[k] = (u < UU) ? __expf(UA[u * KK + k]) : 0.f;
#pragma unroll
    for (int o = 16; o; o >>= 1)
#pragma unroll
        for (int k = 0; k < KK; k++)
            ps[k] += __shfl_xor_sync(0xffffffffu, ps[k], o);
    if (lane == 0)
#pragma unroll
        for (int k = 0; k < KK; k++) sm[wid * KK + k] = ps[k];
    __syncthreads();
    if (t < KK) {
        float s = sm[t];
#pragma unroll
        for (int w = 1; w < 8; w++) s += sm[w * KK + t];
        g_csum_part[blockIdx.x * KK + t] = s;
    }
}

// ---- 2: Wc = softmax(CA, axis=D): block per course, PADDED smem (stride 9) ----
__global__ void k_wc(const float* __restrict__ CA) {
    __shared__ float s[DD * 9];   // 4.5KB, row stride 9
    int c = blockIdx.x, t = threadIdx.x;  // 256 threads
    const float4* src = (const float4*)(CA + (size_t)c * DD * KK);
    float4 v = src[t];
    int base = t * 4;             // base%8 is 0 or 4 -> all 4 in same row d
    int d0 = base >> 3, k0 = base & 7;
    float* sp = s + d0 * 9 + k0;
    sp[0] = v.x; sp[1] = v.y; sp[2] = v.z; sp[3] = v.w;
    __syncthreads();
    int w = t >> 5, lane = t & 31;  // warp w owns behavior column k=w
    float e[4], sum = 0.f;
#pragma unroll
    for (int j = 0; j < 4; j++) {
        int d = lane + 32 * j;
        e[j] = __expf(s[d * 9 + w]);
        sum += e[j];
    }
#pragma unroll
    for (int o = 16; o; o >>= 1) sum += __shfl_xor_sync(0xffffffffu, sum, o);
    float inv = __fdividef(1.f, sum);
#pragma unroll
    for (int j = 0; j < 4; j++) {
        int d = lane + 32 * j;
        s[d * 9 + w] = e[j] * inv;
    }
    __syncthreads();
    float4 o4 = make_float4(sp[0], sp[1], sp[2], sp[3]);
    float4* dst = (float4*)(g_Wc + (size_t)c * DD * KK);
    dst[t] = o4;
}

// ---- 3: A[i,k] = sum_d X[i,d] * Wc[cour[i],d,k] : one warp per TWO samples ----
__global__ void k_a(const float* __restrict__ X, const int* __restrict__ cour, int n) {
    int w = blockIdx.x * (blockDim.x >> 5) + (threadIdx.x >> 5);
    int lane = threadIdx.x & 31;
    int i0 = w * 2;
    if (i0 >= n) return;
    bool two = (i0 + 1 < n);
    int i1 = two ? i0 + 1 : i0;
    int ca = __ldg(cour + i0), cb = __ldg(cour + i1);
    const float* xr0 = X + (size_t)i0 * DD;
    const float* xr1 = X + (size_t)i1 * DD;
    float x0[4], x1[4];
#pragma unroll
    for (int j = 0; j < 4; j++) {
        x0[j] = xr0[lane + 32 * j];
        x1[j] = xr1[lane + 32 * j];
    }
    const float* wa = g_Wc + (size_t)ca * DD * KK;
    const float* wb = g_Wc + (size_t)cb * DD * KK;
    float A0[KK], A1[KK];
#pragma unroll
    for (int k = 0; k < KK; k++) { A0[k] = 0.f; A1[k] = 0.f; }
#pragma unroll
    for (int j = 0; j < 4; j++) {
        int d = lane + 32 * j;
        float4 p0 = *(const float4*)(wa + d * KK);
        float4 p1 = *(const float4*)(wa + d * KK + 4);
        float4 q0 = *(const float4*)(wb + d * KK);
        float4 q1 = *(const float4*)(wb + d * KK + 4);
        A0[0] = fmaf(x0[j], p0.x, A0[0]); A0[1] = fmaf(x0[j], p0.y, A0[1]);
        A0[2] = fmaf(x0[j], p0.z, A0[2]); A0[3] = fmaf(x0[j], p0.w, A0[3]);
        A0[4] = fmaf(x0[j], p1.x, A0[4]); A0[5] = fmaf(x0[j], p1.y, A0[5]);
        A0[6] = fmaf(x0[j], p1.z, A0[6]); A0[7] = fmaf(x0[j], p1.w, A0[7]);
        A1[0] = fmaf(x1[j], q0.x, A1[0]); A1[1] = fmaf(x1[j], q0.y, A1[1]);
        A1[2] = fmaf(x1[j], q0.z, A1[2]); A1[3] = fmaf(x1[j], q0.w, A1[3]);
        A1[4] = fmaf(x1[j], q1.x, A1[4]); A1[5] = fmaf(x1[j], q1.y, A1[5]);
        A1[6] = fmaf(x1[j], q1.z, A1[6]); A1[7] = fmaf(x1[j], q1.w, A1[7]);
    }
#pragma unroll
    for (int o = 16; o; o >>= 1)
#pragma unroll
        for (int k = 0; k < KK; k++) {
            A0[k] += __shfl_xor_sync(0xffffffffu, A0[k], o);
            A1[k] += __shfl_xor_sync(0xffffffffu, A1[k], o);
        }
    if (lane == 0) {
        float4* ar = (float4*)(g_A + (size_t)i0 * KK);
        ar[0] = make_float4(A0[0], A0[1], A0[2], A0[3]);
        ar[1] = make_float4(A0[4], A0[5], A0[6], A0[7]);
        if (two) {
            float4* br = (float4*)(g_A + (size_t)i1 * KK);
            br[0] = make_float4(A1[0], A1[1], A1[2], A1[3]);
            br[1] = make_float4(A1[4], A1[5], A1[6], A1[7]);
        }
    }
}

// ---- 4: Q partials. TWO rows per barrier: halves barrier count, ILP=2 on the
//         shuffle chains. exp consumes prefetch regs directly (no copies). ----
__global__ void __launch_bounds__(256, 2) k_q(const float* __restrict__ UC,
                                              const float* __restrict__ UA, int rpb) {
    __shared__ float red[2][2][8];
    __shared__ __align__(8) float sua[2][2][8];
    int t = threadIdx.x, lane = t & 31, wid = t >> 5;
    int c0 = t * 8;
    bool act = (c0 < CC);
    ull q[32];  // q[j*4+p] = (Q[c0+j][2p], Q[c0+j][2p+1]) partial
#pragma unroll
    for (int j = 0; j < 32; j++) q[j] = 0ull;

    int u0 = blockIdx.x * rpb;
    int u1 = u0 + rpb; if (u1 > UU) u1 = UU;
    int nrows = u1 - u0;
    int npairs = nrows >> 1;

    float4 pa0, pa1, pb0, pb1;
    pa0 = pa1 = pb0 = pb1 = make_float4(0, 0, 0, 0);
    if (act && npairs > 0) {
        const float* r0 = UC + (size_t)u0 * CC + c0;
        pa0 = *(const float4*)r0;        pa1 = *(const float4*)(r0 + 4);
        pb0 = *(const float4*)(r0 + CC); pb1 = *(const float4*)(r0 + CC + 4);
    }
    if (t < 16 && npairs > 0) {
        int r = t >> 3, k = t & 7;
        sua[0][r][k] = __expf(UA[(size_t)(u0 + r) * KK + k]);
    }
    int par = 0;
    for (int p = 0; p < npairs; ++p, par ^= 1) {
        int u = u0 + 2 * p;
        float e0[8], e1[8], ls0 = 0.f, ls1 = 0.f;
        if (act) {
            e0[0] = __expf(pa0.x); e0[1] = __expf(pa0.y);
            e0[2] = __expf(pa0.z); e0[3] = __expf(pa0.w);
            e0[4] = __expf(pa1.x); e0[5] = __expf(pa1.y);
            e0[6] = __expf(pa1.z); e0[7] = __expf(pa1.w);
            e1[0] = __expf(pb0.x); e1[1] = __expf(pb0.y);
            e1[2] = __expf(pb0.z); e1[3] = __expf(pb0.w);
            e1[4] = __expf(pb1.x); e1[5] = __expf(pb1.y);
            e1[6] = __expf(pb1.z); e1[7] = __expf(pb1.w);
        } else {
#pragma unroll
            for (int j = 0; j < 8; j++) { e0[j] = 0.f; e1[j] = 0.f; }
        }
        if (act && p + 1 < npairs) {  // prefetch next row pair
            const float* r0 = UC + (size_t)(u + 2) * CC + c0;
            pa0 = *(const float4*)r0;        pa1 = *(const float4*)(r0 + 4);
            pb0 = *(const float4*)(r0 + CC); pb1 = *(const float4*)(r0 + CC + 4);
        }
#pragma unroll
        for (int j = 0; j < 8; j++) { ls0 += e0[j]; ls1 += e1[j]; }
#pragma unroll
        for (int o = 16; o; o >>= 1) {
            ls0 += __shfl_xor_sync(0xffffffffu, ls0, o);
            ls1 += __shfl_xor_sync(0xffffffffu, ls1, o);
        }
        if (lane == 0) { red[par][0][wid] = ls0; red[par][1][wid] = ls1; }
        __syncthreads();
        // stage next pair's UA AFTER the barrier (read after the NEXT barrier)
        if (t < 16 && p + 1 < npairs) {
            int r = t >> 3, k = t & 7;
            sua[par ^ 1][r][k] = __expf(UA[(size_t)(u + 2 + r) * KK + k]);
        }
        float s0 = 0.f, s1 = 0.f;
#pragma unroll
        for (int w = 0; w < 8; w++) { s0 += red[par][0][w]; s1 += red[par][1][w]; }
        float inv0 = __fdividef(1.f, s0), inv1 = __fdividef(1.f, s1);
        ull i0p = pack2(inv0, inv0), i1p = pack2(inv1, inv1);
        const ull* sp0 = (const ull*)sua[par][0];
        const ull* sp1 = (const ull*)sua[par][1];
        ull ua0[4], ua1[4];
#pragma unroll
        for (int pp = 0; pp < 4; pp++) {
            ua0[pp] = mul2(sp0[pp], i0p);
            ua1[pp] = mul2(sp1[pp], i1p);
        }
        if (act) {
#pragma unroll
            for (int j = 0; j < 8; j++) {
                ull e0p = pack2(e0[j], e0[j]);
                ull e1p = pack2(e1[j], e1[j]);
#pragma unroll
                for (int pp = 0; pp < 4; pp++) {
                    q[j * 4 + pp] = fma2(e0p, ua0[pp], q[j * 4 + pp]);
                    q[j * 4 + pp] = fma2(e1p, ua1[pp], q[j * 4 + pp]);
                }
            }
        }
    }
    // odd tail row (not hit with current config; kept for safety)
    if (nrows & 1) {
        int u = u1 - 1;
        float e[8], ls = 0.f;
        if (act) {
            const float* r = UC + (size_t)u * CC + c0;
            float4 a = *(const float4*)r, b = *(const float4*)(r + 4);
            e[0] = __expf(a.x); e[1] = __expf(a.y); e[2] = __expf(a.z); e[3] = __expf(a.w);
            e[4] = __expf(b.x); e[5] = __expf(b.y); e[6] = __expf(b.z); e[7] = __expf(b.w);
        } else {
#pragma unroll
            for (int j = 0; j < 8; j++) e[j] = 0.f;
        }
#pragma unroll
        for (int j = 0; j < 8; j++) ls += e[j];
#pragma unroll
        for (int o = 16; o; o >>= 1) ls += __shfl_xor_sync(0xffffffffu, ls, o);
        if (lane == 0) red[par][0][wid] = ls;
        if (t < KK) sua[par][0][t] = __expf(UA[(size_t)u * KK + t]);
        __syncthreads();
        float s = 0.f;
#pragma unroll
        for (int w = 0; w < 8; w++) s += red[par][0][w];
        float inv = __fdividef(1.f, s);
        ull invp = pack2(inv, inv);
        const ull* sp = (const ull*)sua[par][0];
        ull uap[4];
#pragma unroll
        for (int pp = 0; pp < 4; pp++) uap[pp] = mul2(sp[pp], invp);
        if (act) {
#pragma unroll
            for (int j = 0; j < 8; j++) {
                ull ep = pack2(e[j], e[j]);
#pragma unroll
                for (int pp = 0; pp < 4; pp++)
                    q[j * 4 + pp] = fma2(ep, uap[pp], q[j * 4 + pp]);
            }
        }
    }
    if (act) {
        float* dst = g_Qpart + (size_t)blockIdx.x * CK + (size_t)c0 * KK;
#pragma unroll
        for (int j = 0; j < 8; j++) {
            ulonglong2 v0; v0.x = q[j * 4 + 0]; v0.y = q[j * 4 + 1];
            ulonglong2 v1; v1.x = q[j * 4 + 2]; v1.y = q[j * 4 + 3];
            *(ulonglong2*)(dst + j * 8)     = v0;
            *(ulonglong2*)(dst + j * 8 + 4) = v1;
        }
    }
}

// ---- 5: reduce partials (float4) + csum normalization + sigmoid fold ----
__global__ void k_fold(const float* __restrict__ guess_, const float* __restrict__ slide_) {
    __shared__ float sinv[KK];
    if (threadIdx.x < KK) {
        float s = 0.f;
        for (int b = 0; b < UASB; b++) s += g_csum_part[b * KK + threadIdx.x];
        sinv[threadIdx.x] = __fdividef(1.f, s);
    }
    __syncthreads();
    int g4 = blockIdx.x * blockDim.x + threadIdx.x;
    if (g4 >= CK / 4) return;
    int i = g4 * 4;
    float4 s = make_float4(0, 0, 0, 0);
#pragma unroll 4
    for (int b = 0; b < QB; b++) {
        float4 v = *(const float4*)(g_Qpart + (size_t)b * CK + i);
        s.x += v.x; s.y += v.y; s.z += v.z; s.w += v.w;
    }
    int c = i >> 3, k = i & 7;   // k is 0 or 4
    float g  = __fdividef(1.f, 1.f + __expf(-guess_[c]));
    float sl = __fdividef(1.f, 1.f + __expf(-slide_[c]));
    float sc = 1.f - sl - g;
    s.x *= sc * sinv[k];     s.y *= sc * sinv[k + 1];
    s.z *= sc * sinv[k + 2]; s.w *= sc * sinv[k + 3];
    *(float4*)(g_Qs + i) = s;
    if (k == 0) g_gb[c] = g;
}

// ---- 6: Y[i,c] = gb[c] + A[i,:]·Qs[c,:]  (unchanged from 214.8 build;
//         launcher uses yrpb=76 -> 1316 blocks = 2.96 waves at 3 blocks/SM) ----
__global__ void __launch_bounds__(256, 3) k_y(float* __restrict__ Y, int rpb, int n) {
    int t = threadIdx.x;
    int c0 = blockIdx.y * 1024 + t * 4;
    if (c0 >= CC) return;  // no syncs in this kernel; early exit is safe
    ull q2[16], gb2[2];    // q2[p*8+k] = (Qs[c0+2p][k], Qs[c0+2p+1][k])
    {
        float qs[32];
        const float4* qp = (const float4*)(g_Qs + (size_t)c0 * KK);
#pragma unroll
        for (int j = 0; j < 8; j++) {
            float4 r = qp[j];
            qs[j * 4 + 0] = r.x; qs[j * 4 + 1] = r.y;
            qs[j * 4 + 2] = r.z; qs[j * 4 + 3] = r.w;
        }
#pragma unroll
        for (int p = 0; p < 2; p++)
#pragma unroll
            for (int k = 0; k < 8; k++)
                q2[p * 8 + k] = pack2(qs[(2 * p) * 8 + k], qs[(2 * p + 1) * 8 + k]);
        float4 b = *(const float4*)(g_gb + c0);
        gb2[0] = pack2(b.x, b.y); gb2[1] = pack2(b.z, b.w);
    }
    int i0 = blockIdx.x * rpb;
    int i1 = i0 + rpb; if (i1 > n) i1 = n;
    if (i0 >= i1) return;

    int ra = i0, rb = (i0 + 1 < i1) ? i0 + 1 : i1 - 1;
    const float4* pa = (const float4*)(g_A + (size_t)ra * KK);
    const float4* pb = (const float4*)(g_A + (size_t)rb * KK);
    float4 a00 = pa[0], a01 = pa[1], a10 = pb[0], a11 = pb[1];

    int i = i0;
    for (; i + 2 <= i1; i += 2) {
        float4 c00 = a00, c01 = a01, c10 = a10, c11 = a11;
        {   // prefetch next pair
            int na = (i + 2 < i1) ? i + 2 : i1 - 1;
            int nb = (i + 3 < i1) ? i + 3 : i1 - 1;
            const float4* qa = (const float4*)(g_A + (size_t)na * KK);
            const float4* qb = (const float4*)(g_A + (size_t)nb * KK);
            a00 = qa[0]; a01 = qa[1]; a10 = qb[0]; a11 = qb[1];
        }
        {
            ull acc0 = gb2[0], acc1 = gb2[1], ap;
            ap = pack2(c00.x, c00.x); acc0 = fma2(ap, q2[0], acc0); acc1 = fma2(ap, q2[8],  acc1);
            ap = pack2(c00.y, c00.y); acc0 = fma2(ap, q2[1], acc0); acc1 = fma2(ap, q2[9],  acc1);
            ap = pack2(c00.z, c00.z); acc0 = fma2(ap, q2[2], acc0); acc1 = fma2(ap, q2[10], acc1);
            ap = pack2(c00.w, c00.w); acc0 = fma2(ap, q2[3], acc0); acc1 = fma2(ap, q2[11], acc1);
            ap = pack2(c01.x, c01.x); acc0 = fma2(ap, q2[4], acc0); acc1 = fma2(ap, q2[12], acc1);
            ap = pack2(c01.y, c01.y); acc0 = fma2(ap, q2[5], acc0); acc1 = fma2(ap, q2[13], acc1);
            ap = pack2(c01.z, c01.z); acc0 = fma2(ap, q2[6], acc0); acc1 = fma2(ap, q2[14], acc1);
            ap = pack2(c01.w, c01.w); acc0 = fma2(ap, q2[7], acc0); acc1 = fma2(ap, q2[15], acc1);
            ulonglong2 s; s.x = acc0; s.y = acc1;
            *(ulonglong2*)(Y + (size_t)i * CC + c0) = s;
        }
        {
            ull acc0 = gb2[0], acc1 = gb2[1], ap;
            ap = pack2(c10.x, c10.x); acc0 = fma2(ap, q2[0], acc0); acc1 = fma2(ap, q2[8],  acc1);
            ap = pack2(c10.y, c10.y); acc0 = fma2(ap, q2[1], acc0); acc1 = fma2(ap, q2[9],  acc1);
            ap = pack2(c10.z, c10.z); acc0 = fma2(ap, q2[2], acc0); acc1 = fma2(ap, q2[10], acc1);
            ap = pack2(c10.w, c10.w); acc0 = fma2(ap, q2[3], acc0); acc1 = fma2(ap, q2[11], acc1);
            ap = pack2(c11.x, c11.x); acc0 = fma2(ap, q2[4], acc0); acc1 = fma2(ap, q2[12], acc1);
            ap = pack2(c11.y, c11.y); acc0 = fma2(ap, q2[5], acc0); acc1 = fma2(ap, q2[13], acc1);
            ap = pack2(c11.z, c11.z); acc0 = fma2(ap, q2[6], acc0); acc1 = fma2(ap, q2[14], acc1);
            ap = pack2(c11.w, c11.w); acc0 = fma2(ap, q2[7], acc0); acc1 = fma2(ap, q2[15], acc1);
            ulonglong2 s; s.x = acc0; s.y = acc1;
            *(ulonglong2*)(Y + (size_t)(i + 1) * CC + c0) = s;
        }
    }
    if (i < i1) {
        const float4* ap4 = (const float4*)(g_A + (size_t)i * KK);
        float4 c00 = ap4[0], c01 = ap4[1];
        ull acc0 = gb2[0], acc1 = gb2[1], ap;
        ap = pack2(c00.x, c00.x); acc0 = fma2(ap, q2[0], acc0); acc1 = fma2(ap, q2[8],  acc1);
        ap = pack2(c00.y, c00.y); acc0 = fma2(ap, q2[1], acc0); acc1 = fma2(ap, q2[9],  acc1);
        ap = pack2(c00.z, c00.z); acc0 = fma2(ap, q2[2], acc0); acc1 = fma2(ap, q2[10], acc1);
        ap = pack2(c00.w, c00.w); acc0 = fma2(ap, q2[3], acc0); acc1 = fma2(ap, q2[11], acc1);
        ap = pack2(c01.x, c01.x); acc0 = fma2(ap, q2[4], acc0); acc1 = fma2(ap, q2[12], acc1);
        ap = pack2(c01.y, c01.y); acc0 = fma2(ap, q2[5], acc0); acc1 = fma2(ap, q2[13], acc1);
        ap = pack2(c01.z, c01.z); acc0 = fma2(ap, q2[6], acc0); acc1 = fma2(ap, q2[14], acc1);
        ap = pack2(c01.w, c01.w); acc0 = fma2(ap, q2[7], acc0); acc1 = fma2(ap, q2[15], acc1);
        ulonglong2 s; s.x = acc0; s.y = acc1;
        *(ulonglong2*)(Y + (size_t)i * CC + c0) = s;
    }
}

extern "C" void kernel_launch(void* const* d_in, const int* in_sizes, int n_in,
                              void* d_out, int out_size) {
    const float* X      = (const float*)d_in[0];
    const int*   cour   = (const int*)d_in[1];
    const float* CA     = (const float*)d_in[2];
    const float* UA     = (const float*)d_in[3];
    const float* UC     = (const float*)d_in[4];
    const float* guess_ = (const float*)d_in[5];
    const float* slide_ = (const float*)d_in[6];
    float* Y = (float*)d_out;
    int n = in_sizes[1];  // number of samples

    k_ua_sum<<<UASB, 256>>>(UA);
    k_wc<<<CC, 256>>>(CA);
    int warps = (n + 1) / 2;
    k_a<<<(warps + 7) / 8, 256>>>(X, cour, n);
    int rpb = (UU + QB - 1) / QB;
    k_q<<<QB, 256>>>(UC, UA, rpb);
    k_fold<<<(CK / 4 + 255) / 256, 256>>>(guess_, slide_);
    int yrpb = 76;   // 2*ceil(50000/76)=1316 blocks ~= 2.96 waves @ 3 blocks/SM
    dim3 ygrid((n + yrpb - 1) / yrpb, 2);
    k_y<<<ygrid, 256>>>(Y, yrpb, n);
}

// round 16
// speedup vs baseline: 1.8873x; 1.0112x over previous
#include <cuda_runtime.h>

#define DD 128
#define KK 8
#define CC 2000
#define UU 20000
#define NN_MAX 50000
#define QB 296                 // blocks in k_q (2 per SM on 148 SMs)
#define CK (CC * KK)           // 16000
#define UASB 79                // k_ua_sum blocks = ceil(20000/256)

typedef unsigned long long ull;

// ---- scratch (device globals; no allocation allowed) ----
__device__ float g_Wc[CC * KK * DD];     // softmax(CA) TRANSPOSED: [c][k][d]
__device__ float g_A[NN_MAX * KK];       // pooled activity features
__device__ float g_csum_part[UASB * KK]; // per-block colsum(exp(UA)) partials
__device__ float g_Qpart[QB * CK];       // per-block Q partials
__device__ float g_Qs[CK];               // (1 - slide - guess) * Q / csum
__device__ float g_gb[CC];               // guess bias

// ---- f32x2 packed helpers (FFMA2 only reachable via PTX) ----
__device__ __forceinline__ ull pack2(float lo, float hi) {
    ull r;
    asm("mov.b64 %0, {%1, %2};" : "=l"(r) : "f"(lo), "f"(hi));
    return r;
}
__device__ __forceinline__ ull fma2(ull a, ull b, ull c) {
    ull d;
    asm("fma.rn.f32x2 %0, %1, %2, %3;" : "=l"(d) : "l"(a), "l"(b), "l"(c));
    return d;
}
__device__ __forceinline__ ull mul2(ull a, ull b) {
    ull d;
    asm("mul.rn.f32x2 %0, %1, %2;" : "=l"(d) : "l"(a), "l"(b));
    return d;
}

// ---- 1: per-block colsum of exp(UA) partials (no init, no atomics) ----
__global__ void k_ua_sum(const float* __restrict__ UA) {
    __shared__ float sm[8 * KK];
    int t = threadIdx.x, lane = t & 31, wid = t >> 5;
    int u = blockIdx.x * blockDim.x + t;
    float ps[KK];
#pragma unroll
    for (int k = 0; k < KK; k++)
        ps[k] = (u < UU) ? __expf(UA[u * KK + k]) : 0.f;
#pragma unroll
    for (int o = 16; o; o >>= 1)
#pragma unroll
        for (int k = 0; k < KK; k++)
            ps[k] += __shfl_xor_sync(0xffffffffu, ps[k], o);
    if (lane == 0)
#pragma unroll
        for (int k = 0; k < KK; k++) sm[wid * KK + k] = ps[k];
    __syncthreads();
    if (t < KK) {
        float s = sm[t];
#pragma unroll
        for (int w = 1; w < 8; w++) s += sm[w * KK + t];
        g_csum_part[blockIdx.x * KK + t] = s;
    }
}

// ---- 2: Wc = softmax(CA, axis=D), stored TRANSPOSED [c][k][d].
//         Warp w owns k=w; output write is register->gmem, fully coalesced. ----
__global__ void k_wc(const float* __restrict__ CA) {
    __shared__ float s[DD * 9];   // 4.5KB, row stride 9 (conflict-free columns)
    int c = blockIdx.x, t = threadIdx.x;  // 256 threads
    const float4* src = (const float4*)(CA + (size_t)c * DD * KK);
    float4 v = src[t];
    int base = t * 4;             // base%8 is 0 or 4 -> all 4 in same row d
    int d0 = base >> 3, k0 = base & 7;
    float* sp = s + d0 * 9 + k0;
    sp[0] = v.x; sp[1] = v.y; sp[2] = v.z; sp[3] = v.w;
    __syncthreads();
    int w = t >> 5, lane = t & 31;  // warp w owns behavior column k=w
    float e[4], sum = 0.f;
#pragma unroll
    for (int j = 0; j < 4; j++) {
        int d = lane + 32 * j;
        e[j] = __expf(s[d * 9 + w]);
        sum += e[j];
    }
#pragma unroll
    for (int o = 16; o; o >>= 1) sum += __shfl_xor_sync(0xffffffffu, sum, o);
    float inv = __fdividef(1.f, sum);
    float* dst = g_Wc + (size_t)c * KK * DD + w * DD;  // [c][k=w][.]
#pragma unroll
    for (int j = 0; j < 4; j++)
        dst[lane + 32 * j] = e[j] * inv;   // coalesced 128B per warp-store
}

// ---- 3: A[i,k] = sum_d X[i,d] * WcT[cour[i],k,d] : warp per TWO samples.
//         All loads coalesced float4 (nL=4), fixing the nL=32 scatter. ----
__global__ void k_a(const float* __restrict__ X, const int* __restrict__ cour, int n) {
    int w = blockIdx.x * (blockDim.x >> 5) + (threadIdx.x >> 5);
    int lane = threadIdx.x & 31;
    int i0 = w * 2;
    if (i0 >= n) return;
    bool two = (i0 + 1 < n);
    int i1 = two ? i0 + 1 : i0;
    int ca = __ldg(cour + i0), cb = __ldg(cour + i1);
    float4 x0 = ((const float4*)(X + (size_t)i0 * DD))[lane];  // d = 4*lane..+3
    float4 x1 = ((const float4*)(X + (size_t)i1 * DD))[lane];
    const float* wa = g_Wc + (size_t)ca * KK * DD;
    const float* wb = g_Wc + (size_t)cb * KK * DD;
    float A0[KK], A1[KK];
#pragma unroll
    for (int k = 0; k < KK; k++) {
        float4 va = ((const float4*)(wa + k * DD))[lane];
        float4 vb = ((const float4*)(wb + k * DD))[lane];
        A0[k] = fmaf(x0.x, va.x, fmaf(x0.y, va.y, fmaf(x0.z, va.z, x0.w * va.w)));
        A1[k] = fmaf(x1.x, vb.x, fmaf(x1.y, vb.y, fmaf(x1.z, vb.z, x1.w * vb.w)));
    }
#pragma unroll
    for (int o = 16; o; o >>= 1)
#pragma unroll
        for (int k = 0; k < KK; k++) {
            A0[k] += __shfl_xor_sync(0xffffffffu, A0[k], o);
            A1[k] += __shfl_xor_sync(0xffffffffu, A1[k], o);
        }
    if (lane == 0) {
        float4* ar = (float4*)(g_A + (size_t)i0 * KK);
        ar[0] = make_float4(A0[0], A0[1], A0[2], A0[3]);
        ar[1] = make_float4(A0[4], A0[5], A0[6], A0[7]);
        if (two) {
            float4* br = (float4*)(g_A + (size_t)i1 * KK);
            br[0] = make_float4(A1[0], A1[1], A1[2], A1[3]);
            br[1] = make_float4(A1[4], A1[5], A1[6], A1[7]);
        }
    }
}

// ---- 4: Q partials. TWO rows per barrier (measured 48.4us; unchanged). ----
__global__ void __launch_bounds__(256, 2) k_q(const float* __restrict__ UC,
                                              const float* __restrict__ UA, int rpb) {
    __shared__ float red[2][2][8];
    __shared__ __align__(8) float sua[2][2][8];
    int t = threadIdx.x, lane = t & 31, wid = t >> 5;
    int c0 = t * 8;
    bool act = (c0 < CC);
    ull q[32];  // q[j*4+p] = (Q[c0+j][2p], Q[c0+j][2p+1]) partial
#pragma unroll
    for (int j = 0; j < 32; j++) q[j] = 0ull;

    int u0 = blockIdx.x * rpb;
    int u1 = u0 + rpb; if (u1 > UU) u1 = UU;
    int nrows = u1 - u0;
    int npairs = nrows >> 1;

    float4 pa0, pa1, pb0, pb1;
    pa0 = pa1 = pb0 = pb1 = make_float4(0, 0, 0, 0);
    if (act && npairs > 0) {
        const float* r0 = UC + (size_t)u0 * CC + c0;
        pa0 = *(const float4*)r0;        pa1 = *(const float4*)(r0 + 4);
        pb0 = *(const float4*)(r0 + CC); pb1 = *(const float4*)(r0 + CC + 4);
    }
    if (t < 16 && npairs > 0) {
        int r = t >> 3, k = t & 7;
        sua[0][r][k] = __expf(UA[(size_t)(u0 + r) * KK + k]);
    }
    int par = 0;
    for (int p = 0; p < npairs; ++p, par ^= 1) {
        int u = u0 + 2 * p;
        float e0[8], e1[8], ls0 = 0.f, ls1 = 0.f;
        if (act) {
            e0[0] = __expf(pa0.x); e0[1] = __expf(pa0.y);
            e0[2] = __expf(pa0.z); e0[3] = __expf(pa0.w);
            e0[4] = __expf(pa1.x); e0[5] = __expf(pa1.y);
            e0[6] = __expf(pa1.z); e0[7] = __expf(pa1.w);
            e1[0] = __expf(pb0.x); e1[1] = __expf(pb0.y);
            e1[2] = __expf(pb0.z); e1[3] = __expf(pb0.w);
            e1[4] = __expf(pb1.x); e1[5] = __expf(pb1.y);
            e1[6] = __expf(pb1.z); e1[7] = __expf(pb1.w);
        } else {
#pragma unroll
            for (int j = 0; j < 8; j++) { e0[j] = 0.f; e1[j] = 0.f; }
        }
        if (act && p + 1 < npairs) {  // prefetch next row pair
            const float* r0 = UC + (size_t)(u + 2) * CC + c0;
            pa0 = *(const float4*)r0;        pa1 = *(const float4*)(r0 + 4);
            pb0 = *(const float4*)(r0 + CC); pb1 = *(const float4*)(r0 + CC + 4);
        }
#pragma unroll
        for (int j = 0; j < 8; j++) { ls0 += e0[j]; ls1 += e1[j]; }
#pragma unroll
        for (int o = 16; o; o >>= 1) {
            ls0 += __shfl_xor_sync(0xffffffffu, ls0, o);
            ls1 += __shfl_xor_sync(0xffffffffu, ls1, o);
        }
        if (lane == 0) { red[par][0][wid] = ls0; red[par][1][wid] = ls1; }
        __syncthreads();
        // stage next pair's UA AFTER the barrier (read after the NEXT barrier)
        if (t < 16 && p + 1 < npairs) {
            int r = t >> 3, k = t & 7;
            sua[par ^ 1][r][k] = __expf(UA[(size_t)(u + 2 + r) * KK + k]);
        }
        float s0 = 0.f, s1 = 0.f;
#pragma unroll
        for (int w = 0; w < 8; w++) { s0 += red[par][0][w]; s1 += red[par][1][w]; }
        float inv0 = __fdividef(1.f, s0), inv1 = __fdividef(1.f, s1);
        ull i0p = pack2(inv0, inv0), i1p = pack2(inv1, inv1);
        const ull* sp0 = (const ull*)sua[par][0];
        const ull* sp1 = (const ull*)sua[par][1];
        ull ua0[4], ua1[4];
#pragma unroll
        for (int pp = 0; pp < 4; pp++) {
            ua0[pp] = mul2(sp0[pp], i0p);
            ua1[pp] = mul2(sp1[pp], i1p);
        }
        if (act) {
#pragma unroll
            for (int j = 0; j < 8; j++) {
                ull e0p = pack2(e0[j], e0[j]);
                ull e1p = pack2(e1[j], e1[j]);
#pragma unroll
                for (int pp = 0; pp < 4; pp++) {
                    q[j * 4 + pp] = fma2(e0p, ua0[pp], q[j * 4 + pp]);
                    q[j * 4 + pp] = fma2(e1p, ua1[pp], q[j * 4 + pp]);
                }
            }
        }
    }
    // odd tail row (not hit with current config; kept for safety)
    if (nrows & 1) {
        int u = u1 - 1;
        float e[8], ls = 0.f;
        if (act) {
            const float* r = UC + (size_t)u * CC + c0;
            float4 a = *(const float4*)r, b = *(const float4*)(r + 4);
            e[0] = __expf(a.x); e[1] = __expf(a.y); e[2] = __expf(a.z); e[3] = __expf(a.w);
            e[4] = __expf(b.x); e[5] = __expf(b.y); e[6] = __expf(b.z); e[7] = __expf(b.w);
        } else {
#pragma unroll
            for (int j = 0; j < 8; j++) e[j] = 0.f;
        }
#pragma unroll
        for (int j = 0; j < 8; j++) ls += e[j];
#pragma unroll
        for (int o = 16; o; o >>= 1) ls += __shfl_xor_sync(0xffffffffu, ls, o);
        if (lane == 0) red[par][0][wid] = ls;
        if (t < KK) sua[par][0][t] = __expf(UA[(size_t)u * KK + t]);
        __syncthreads();
        float s = 0.f;
#pragma unroll
        for (int w = 0; w < 8; w++) s += red[par][0][w];
        float inv = __fdividef(1.f, s);
        ull invp = pack2(inv, inv);
        const ull* sp = (const ull*)sua[par][0];
        ull uap[4];
#pragma unroll
        for (int pp = 0; pp < 4; pp++) uap[pp] = mul2(sp[pp], invp);
        if (act) {
#pragma unroll
            for (int j = 0; j < 8; j++) {
                ull ep = pack2(e[j], e[j]);
#pragma unroll
                for (int pp = 0; pp < 4; pp++)
                    q[j * 4 + pp] = fma2(ep, uap[pp], q[j * 4 + pp]);
            }
        }
    }
    if (act) {
        float* dst = g_Qpart + (size_t)blockIdx.x * CK + (size_t)c0 * KK;
#pragma unroll
        for (int j = 0; j < 8; j++) {
            ulonglong2 v0; v0.x = q[j * 4 + 0]; v0.y = q[j * 4 + 1];
            ulonglong2 v1; v1.x = q[j * 4 + 2]; v1.y = q[j * 4 + 3];
            *(ulonglong2*)(dst + j * 8)     = v0;
            *(ulonglong2*)(dst + j * 8 + 4) = v1;
        }
    }
}

// ---- 5: reduce partials (float4) + csum normalization + sigmoid fold ----
__global__ void k_fold(const float* __restrict__ guess_, const float* __restrict__ slide_) {
    __shared__ float sinv[KK];
    if (threadIdx.x < KK) {
        float s = 0.f;
        for (int b = 0; b < UASB; b++) s += g_csum_part[b * KK + threadIdx.x];
        sinv[threadIdx.x] = __fdividef(1.f, s);
    }
    __syncthreads();
    int g4 = blockIdx.x * blockDim.x + threadIdx.x;
    if (g4 >= CK / 4) return;
    int i = g4 * 4;
    float4 s = make_float4(0, 0, 0, 0);
#pragma unroll 4
    for (int b = 0; b < QB; b++) {
        float4 v = *(const float4*)(g_Qpart + (size_t)b * CK + i);
        s.x += v.x; s.y += v.y; s.z += v.z; s.w += v.w;
    }
    int c = i >> 3, k = i & 7;   // k is 0 or 4
    float g  = __fdividef(1.f, 1.f + __expf(-guess_[c]));
    float sl = __fdividef(1.f, 1.f + __expf(-slide_[c]));
    float sc = 1.f - sl - g;
    s.x *= sc * sinv[k];     s.y *= sc * sinv[k + 1];
    s.z *= sc * sinv[k + 2]; s.w *= sc * sinv[k + 3];
    *(float4*)(g_Qs + i) = s;
    if (k == 0) g_gb[c] = g;
}

// ---- 6: Y[i,c] = gb[c] + A[i,:]·Qs[c,:] (measured-good; unchanged) ----
__global__ void __launch_bounds__(256, 3) k_y(float* __restrict__ Y, int rpb, int n) {
    int t = threadIdx.x;
    int c0 = blockIdx.y * 1024 + t * 4;
    if (c0 >= CC) return;  // no syncs in this kernel; early exit is safe
    ull q2[16], gb2[2];    // q2[p*8+k] = (Qs[c0+2p][k], Qs[c0+2p+1][k])
    {
        float qs[32];
        const float4* qp = (const float4*)(g_Qs + (size_t)c0 * KK);
#pragma unroll
        for (int j = 0; j < 8; j++) {
            float4 r = qp[j];
            qs[j * 4 + 0] = r.x; qs[j * 4 + 1] = r.y;
            qs[j * 4 + 2] = r.z; qs[j * 4 + 3] = r.w;
        }
#pragma unroll
        for (int p = 0; p < 2; p++)
#pragma unroll
            for (int k = 0; k < 8; k++)
                q2[p * 8 + k] = pack2(qs[(2 * p) * 8 + k], qs[(2 * p + 1) * 8 + k]);
        float4 b = *(const float4*)(g_gb + c0);
        gb2[0] = pack2(b.x, b.y); gb2[1] = pack2(b.z, b.w);
    }
    int i0 = blockIdx.x * rpb;
    int i1 = i0 + rpb; if (i1 > n) i1 = n;
    if (i0 >= i1) return;

    int ra = i0, rb = (i0 + 1 < i1) ? i0 + 1 : i1 - 1;
    const float4* pa = (const float4*)(g_A + (size_t)ra * KK);
    const float4* pb = (const float4*)(g_A + (size_t)rb * KK);
    float4 a00 = pa[0], a01 = pa[1], a10 = pb[0], a11 = pb[1];

    int i = i0;
    for (; i + 2 <= i1; i += 2) {
        float4 c00 = a00, c01 = a01, c10 = a10, c11 = a11;
        {   // prefetch next pair
            int na = (i + 2 < i1) ? i + 2 : i1 - 1;
            int nb = (i + 3 < i1) ? i + 3 : i1 - 1;
            const float4* qa = (const float4*)(g_A + (size_t)na * KK);
            const float4* qb = (const float4*)(g_A + (size_t)nb * KK);
            a00 = qa[0]; a01 = qa[1]; a10 = qb[0]; a11 = qb[1];
        }
        {
            ull acc0 = gb2[0], acc1 = gb2[1], ap;
            ap = pack2(c00.x, c00.x); acc0 = fma2(ap, q2[0], acc0); acc1 = fma2(ap, q2[8],  acc1);
            ap = pack2(c00.y, c00.y); acc0 = fma2(ap, q2[1], acc0); acc1 = fma2(ap, q2[9],  acc1);
            ap = pack2(c00.z, c00.z); acc0 = fma2(ap, q2[2], acc0); acc1 = fma2(ap, q2[10], acc1);
            ap = pack2(c00.w, c00.w); acc0 = fma2(ap, q2[3], acc0); acc1 = fma2(ap, q2[11], acc1);
            ap = pack2(c01.x, c01.x); acc0 = fma2(ap, q2[4], acc0); acc1 = fma2(ap, q2[12], acc1);
            ap = pack2(c01.y, c01.y); acc0 = fma2(ap, q2[5], acc0); acc1 = fma2(ap, q2[13], acc1);
            ap = pack2(c01.z, c01.z); acc0 = fma2(ap, q2[6], acc0); acc1 = fma2(ap, q2[14], acc1);
            ap = pack2(c01.w, c01.w); acc0 = fma2(ap, q2[7], acc0); acc1 = fma2(ap, q2[15], acc1);
            ulonglong2 s; s.x = acc0; s.y = acc1;
            *(ulonglong2*)(Y + (size_t)i * CC + c0) = s;
        }
        {
            ull acc0 = gb2[0], acc1 = gb2[1], ap;
            ap = pack2(c10.x, c10.x); acc0 = fma2(ap, q2[0], acc0); acc1 = fma2(ap, q2[8],  acc1);
            ap = pack2(c10.y, c10.y); acc0 = fma2(ap, q2[1], acc0); acc1 = fma2(ap, q2[9],  acc1);
            ap = pack2(c10.z, c10.z); acc0 = fma2(ap, q2[2], acc0); acc1 = fma2(ap, q2[10], acc1);
            ap = pack2(c10.w, c10.w); acc0 = fma2(ap, q2[3], acc0); acc1 = fma2(ap, q2[11], acc1);
            ap = pack2(c11.x, c11.x); acc0 = fma2(ap, q2[4], acc0); acc1 = fma2(ap, q2[12], acc1);
            ap = pack2(c11.y, c11.y); acc0 = fma2(ap, q2[5], acc0); acc1 = fma2(ap, q2[13], acc1);
            ap = pack2(c11.z, c11.z); acc0 = fma2(ap, q2[6], acc0); acc1 = fma2(ap, q2[14], acc1);
            ap = pack2(c11.w, c11.w); acc0 = fma2(ap, q2[7], acc0); acc1 = fma2(ap, q2[15], acc1);
            ulonglong2 s; s.x = acc0; s.y = acc1;
            *(ulonglong2*)(Y + (size_t)(i + 1) * CC + c0) = s;
        }
    }
    if (i < i1) {
        const float4* ap4 = (const float4*)(g_A + (size_t)i * KK);
        float4 c00 = ap4[0], c01 = ap4[1];
        ull acc0 = gb2[0], acc1 = gb2[1], ap;
        ap = pack2(c00.x, c00.x); acc0 = fma2(ap, q2[0], acc0); acc1 = fma2(ap, q2[8],  acc1);
        ap = pack2(c00.y, c00.y); acc0 = fma2(ap, q2[1], acc0); acc1 = fma2(ap, q2[9],  acc1);
        ap = pack2(c00.z, c00.z); acc0 = fma2(ap, q2[2], acc0); acc1 = fma2(ap, q2[10], acc1);
        ap = pack2(c00.w, c00.w); acc0 = fma2(ap, q2[3], acc0); acc1 = fma2(ap, q2[11], acc1);
        ap = pack2(c01.x, c01.x); acc0 = fma2(ap, q2[4], acc0); acc1 = fma2(ap, q2[12], acc1);
        ap = pack2(c01.y, c01.y); acc0 = fma2(ap, q2[5], acc0); acc1 = fma2(ap, q2[13], acc1);
        ap = pack2(c01.z, c01.z); acc0 = fma2(ap, q2[6], acc0); acc1 = fma2(ap, q2[14], acc1);
        ap = pack2(c01.w, c01.w); acc0 = fma2(ap, q2[7], acc0); acc1 = fma2(ap, q2[15], acc1);
        ulonglong2 s; s.x = acc0; s.y = acc1;
        *(ulonglong2*)(Y + (size_t)i * CC + c0) = s;
    }
}

extern "C" void kernel_launch(void* const* d_in, const int* in_sizes, int n_in,
                              void* d_out, int out_size) {
    const float* X      = (const float*)d_in[0];
    const int*   cour   = (const int*)d_in[1];
    const float* CA     = (const float*)d_in[2];
    const float* UA     = (const float*)d_in[3];
    const float* UC     = (const float*)d_in[4];
    const float* guess_ = (const float*)d_in[5];
    const float* slide_ = (const float*)d_in[6];
    float* Y = (float*)d_out;
    int n = in_sizes[1];  // number of samples

    k_ua_sum<<<UASB, 256>>>(UA);
    k_wc<<<CC, 256>>>(CA);
    int warps = (n + 1) / 2;
    k_a<<<(warps + 7) / 8, 256>>>(X, cour, n);
    int rpb = (UU + QB - 1) / QB;
    k_q<<<QB, 256>>>(UC, UA, rpb);
    k_fold<<<(CK / 4 + 255) / 256, 256>>>(guess_, slide_);
    int yrpb = 76;   // 2*ceil(50000/76)=1316 blocks ~= 2.96 waves @ 3 blocks/SM
    dim3 ygrid((n + yrpb - 1) / yrpb, 2);
    k_y<<<ygrid, 256>>>(Y, yrpb, n);
}